// round 7
// baseline (speedup 1.0000x reference)
#include <cuda_runtime.h>
#include <cuda_fp16.h>
#include <cstdint>
#include <math.h>

#define Nn 16
#define Hh 256
#define Ww 256
#define HW (Hh*Ww)

// ---------------- scratch (device globals; no allocation allowed) ----------------
__device__ __half g_h2h[(size_t)Nn*HW*64];
__device__ __half g_h2l[(size_t)Nn*HW*64];
__device__ float g_xy[(size_t)Nn*2*HW];
__device__ uint32_t g_wq[9*4*11*32*2];   // prepacked B fragments for current conv

__device__ __forceinline__ void hsplit(float v, unsigned short& h, unsigned short& l) {
    __half hb = __float2half_rn(v);
    float hf = __half2float(hb);
    __half lb = __float2half_rn(v - hf);
    h = __half_as_ushort(hb);
    l = __half_as_ushort(lb);
}
__device__ __forceinline__ float h2f(uint32_t u, int hi) {
    return __half2float(__ushort_as_half((unsigned short)(hi ? (u >> 16) : (u & 0xFFFF))));
}
__device__ __forceinline__ void mma_f16(float* c, const uint32_t* a, uint32_t b0, uint32_t b1) {
    asm volatile("mma.sync.aligned.m16n8k16.row.col.f32.f16.f16.f32 "
        "{%0,%1,%2,%3},{%4,%5,%6,%7},{%8,%9},{%0,%1,%2,%3};"
        : "+f"(c[0]), "+f"(c[1]), "+f"(c[2]), "+f"(c[3])
        : "r"(a[0]), "r"(a[1]), "r"(a[2]), "r"(a[3]), "r"(b0), "r"(b1));
}
__device__ __forceinline__ void ldm_x4(uint32_t* r, uint32_t saddr) {
    asm volatile("ldmatrix.sync.aligned.m8n8.x4.shared.b16 {%0,%1,%2,%3}, [%4];"
        : "=r"(r[0]), "=r"(r[1]), "=r"(r[2]), "=r"(r[3]) : "r"(saddr));
}

// ------------- weight prepack: w[co][ci][3][3] fp32 -> B fragments [tap][k][nt][lane][2]u32 ----
template<int NT, int CO>
__global__ void prepack_wq(const float* __restrict__ w, uint32_t* __restrict__ o) {
    int idx = blockIdx.x * 256 + threadIdx.x;
    if (idx >= 9*4*NT*32) return;
    int lane = idx & 31;
    int nt = (idx >> 5) % NT;
    int k  = (idx / (32*NT)) & 3;
    int tap = idx / (32*NT*4);
    int lg = lane >> 2, lt = lane & 3;
    int co = nt*8 + lg;
    auto wv = [&](int ci) -> uint32_t {
        float v = (co < CO) ? w[((size_t)co*64 + ci)*9 + tap] : 0.f;
        return (uint32_t)__half_as_ushort(__float2half_rn(v));
    };
    int c0 = k*16 + lt*2;
    o[idx*2]   = wv(c0)   | (wv(c0+1) << 16);
    o[idx*2+1] = wv(c0+8) | (wv(c0+9) << 16);
}

// ======== fused conv chain kernel ========
// CIN>0: inline conv1 (CIN->64, relu) computed from fp32 src into A smem tile
//        (ZERO at out-of-image positions = conv2 zero-padding), then 64->CO MMA conv.
// CIN==0: A tile loaded from split-fp16 global buffers.
// FUSE: fused bias+softmax(81)+9x9 pixel-adaptive filter epilogue -> xy.
template<int NT, int CO, int CIN, bool FUSE>
__global__ __launch_bounds__(128) void conv64m(
    const float* __restrict__ src32, const float* __restrict__ w1,
    const float* __restrict__ b1,
    const __half* __restrict__ ihi, const __half* __restrict__ ilo,
    const uint32_t* __restrict__ wq, const float* __restrict__ bias,
    __half* __restrict__ ohi, __half* __restrict__ olo,
    const float* __restrict__ fsrc, float* __restrict__ xy, int sel)
{
    constexpr int CP = NT * 8;
    extern __shared__ char sm[];
    char* sAh = sm;                      // 4 rows x 68 px x 144 B
    char* sAl = sm + 39168;
    float* s_bias = (float*)(sm + 78336);
    float* sx  = (float*)(sm + 78336 + CP*4);             // CIN*6*68 fp32
    float* sw1 = sx + CIN*408;                             // CIN*576
    float* sb1 = sw1 + CIN*576;                            // 64

    int tid = threadIdx.x;
    int lane = tid & 31, wid = tid >> 5;
    int lg = lane >> 2, lt = lane & 3;
    int py = wid >> 1, xb = (wid & 1) * 32;

    int bid = blockIdx.x;                // 16n x 128yp x 4xq
    int xq = bid & 3;
    int yp = (bid >> 2) & 127;
    int n  = bid >> 9;
    int y0 = yp * 2, x0 = xq * 64;
    size_t nbase = (size_t)n * 65536;

    if (tid < CP) s_bias[tid] = (tid < CO) ? bias[tid] : 0.f;

    if constexpr (CIN == 0) {
        // load A tile from split-fp16 global
        for (int idx = tid; idx < 4*66*8; idx += 128) {
            int c = idx & 7, e = idx >> 3;
            int row = e / 66, px = e - row*66;
            int gy = y0 + row - 1, gx = x0 + px - 1;
            uint4 vh = make_uint4(0,0,0,0), vl = vh;
            if ((unsigned)gy < 256u && (unsigned)gx < 256u) {
                size_t pix = nbase + gy*256 + gx;
                vh = *(const uint4*)((const char*)ihi + pix*128 + c*16);
                vl = *(const uint4*)((const char*)ilo + pix*128 + c*16);
            }
            int so = (row*68 + px)*144 + c*16;
            *(uint4*)(sAh + so) = vh;
            *(uint4*)(sAl + so) = vl;
        }
        __syncthreads();
    } else {
        // stage raw fp32 input window (CIN x 6 x 68) + conv1 weights
        for (int idx = tid; idx < CIN*408; idx += 128) {
            int ci = idx / 408, e = idx - ci*408;
            int row = e / 68, col = e - row*68;
            int gy = y0 - 2 + row, gx = x0 - 2 + col;
            float v = 0.f;
            if ((unsigned)gy < 256u && (unsigned)gx < 256u)
                v = src32[((size_t)n*CIN + ci)*HW + gy*256 + gx];
            sx[idx] = v;
        }
        for (int idx = tid; idx < CIN*576; idx += 128) sw1[idx] = w1[idx];
        if (tid < 64) sb1[tid] = b1[tid];
        __syncthreads();

        // inline conv1: compute 4x66 halo of h1, split-fp16 into A tile.
        // Positions OUTSIDE the image must be exactly zero (conv2 zero-padding).
        for (int idx = tid; idx < 264; idx += 128) {
            int r = idx / 66, p = idx - r*66;
            int hy = y0 - 1 + r, hx = x0 - 1 + p;
            char* ph = sAh + (r*68 + p)*144;
            char* pl = sAl + (r*68 + p)*144;
            if ((unsigned)hy >= 256u || (unsigned)hx >= 256u) {
                uint4 z = make_uint4(0,0,0,0);
                #pragma unroll
                for (int q = 0; q < 8; q++) {
                    *(uint4*)(ph + q*16) = z;
                    *(uint4*)(pl + q*16) = z;
                }
                continue;
            }
            float vv[CIN*9];
            #pragma unroll
            for (int ci = 0; ci < CIN; ci++)
                #pragma unroll
                for (int dy = 0; dy < 3; dy++)
                    #pragma unroll
                    for (int dx = 0; dx < 3; dx++)
                        vv[ci*9 + dy*3 + dx] = sx[ci*408 + (r+dy)*68 + (p+dx)];
            #pragma unroll
            for (int q = 0; q < 8; q++) {
                uint32_t hw[4], lw[4];
                #pragma unroll
                for (int t = 0; t < 4; t++) {
                    float o2[2];
                    #pragma unroll
                    for (int j = 0; j < 2; j++) {
                        int co = q*8 + t*2 + j;
                        float s = sb1[co];
                        #pragma unroll
                        for (int i = 0; i < CIN*9; i++) s += sw1[co*CIN*9 + i] * vv[i];
                        o2[j] = fmaxf(s, 0.f);
                    }
                    unsigned short h0, l0, h1_, l1_;
                    hsplit(o2[0], h0, l0); hsplit(o2[1], h1_, l1_);
                    hw[t] = (uint32_t)h0 | ((uint32_t)h1_ << 16);
                    lw[t] = (uint32_t)l0 | ((uint32_t)l1_ << 16);
                }
                *(uint4*)(ph + q*16) = make_uint4(hw[0], hw[1], hw[2], hw[3]);
                *(uint4*)(pl + q*16) = make_uint4(lw[0], lw[1], lw[2], lw[3]);
            }
        }
        __syncthreads();
    }

    float acc[2][NT][4];
    #pragma unroll
    for (int mt = 0; mt < 2; mt++)
        #pragma unroll
        for (int nt = 0; nt < NT; nt++)
            #pragma unroll
            for (int j = 0; j < 4; j++) acc[mt][nt][j] = 0.f;

    uint32_t sA_s = (uint32_t)__cvta_generic_to_shared(sAh);
    uint32_t rbase = (uint32_t)((lane & 15) * 144 + ((lane >> 4) << 4));

    #pragma unroll 1
    for (int tap = 0; tap < 9; tap++) {
        int kh = tap / 3, kw = tap - kh*3;
        uint32_t base0 = sA_s + (uint32_t)(((py + kh)*68 + xb + kw)*144) + rbase;
        const uint32_t* wt = wq + (size_t)tap*4*NT*64 + lane*2;
        #pragma unroll
        for (int k = 0; k < 4; k++) {
            uint32_t ah[2][4], al[2][4];
            #pragma unroll
            for (int mt = 0; mt < 2; mt++) {
                uint32_t ad = base0 + mt*2304 + k*32;
                ldm_x4(ah[mt], ad);
                ldm_x4(al[mt], ad + 39168);
            }
            const uint32_t* wk = wt + (size_t)k*NT*64;
            #pragma unroll
            for (int nt = 0; nt < NT; nt++) {
                uint2 bb = *(const uint2*)(wk + (size_t)nt*64);
                #pragma unroll
                for (int mt = 0; mt < 2; mt++) {
                    mma_f16(acc[mt][nt], ah[mt], bb.x, bb.y);
                    mma_f16(acc[mt][nt], al[mt], bb.x, bb.y);
                }
            }
        }
    }

    if (!FUSE) {
        // bias + relu + split-fp16 global
        #pragma unroll
        for (int mt = 0; mt < 2; mt++) {
            size_t pix0 = nbase + (size_t)(y0 + py)*256 + x0 + xb + mt*16 + lg;
            #pragma unroll
            for (int nt = 0; nt < NT; nt++) {
                int co = nt*8 + lt*2;
                float b0 = s_bias[co], b1v = s_bias[co+1];
                float v00 = fmaxf(acc[mt][nt][0] + b0, 0.f);
                float v01 = fmaxf(acc[mt][nt][1] + b1v, 0.f);
                float v10 = fmaxf(acc[mt][nt][2] + b0, 0.f);
                float v11 = fmaxf(acc[mt][nt][3] + b1v, 0.f);
                unsigned short h0,l0,h1_,l1_;
                hsplit(v00,h0,l0); hsplit(v01,h1_,l1_);
                *(uint32_t*)((char*)ohi + pix0*128 + co*2) = (uint32_t)h0 | ((uint32_t)h1_<<16);
                *(uint32_t*)((char*)olo + pix0*128 + co*2) = (uint32_t)l0 | ((uint32_t)l1_<<16);
                hsplit(v10,h0,l0); hsplit(v11,h1_,l1_);
                *(uint32_t*)((char*)ohi + (pix0+8)*128 + co*2) = (uint32_t)h0 | ((uint32_t)h1_<<16);
                *(uint32_t*)((char*)olo + (pix0+8)*128 + co*2) = (uint32_t)l0 | ((uint32_t)l1_<<16);
            }
        }
    } else {
        // fused softmax over 81 logits + 9x9 pixel-adaptive filtering
        const float* sp = fsrc + nbase;
        int Y = y0 + py;
        #pragma unroll
        for (int mt = 0; mt < 2; mt++) {
            #pragma unroll
            for (int r = 0; r < 2; r++) {
                int X = x0 + xb + mt*16 + lg + r*8;
                float v[NT][2];
                float mx = -1e30f;
                #pragma unroll
                for (int nt = 0; nt < NT; nt++) {
                    #pragma unroll
                    for (int j = 0; j < 2; j++) {
                        int co = nt*8 + lt*2 + j;
                        v[nt][j] = acc[mt][nt][r*2 + j] + s_bias[co];
                        if (co < 81) mx = fmaxf(mx, v[nt][j]);
                    }
                }
                mx = fmaxf(mx, __shfl_xor_sync(0xffffffffu, mx, 1));
                mx = fmaxf(mx, __shfl_xor_sync(0xffffffffu, mx, 2));
                float se = 0.f, fo = 0.f;
                #pragma unroll
                for (int nt = 0; nt < NT; nt++) {
                    #pragma unroll
                    for (int j = 0; j < 2; j++) {
                        int co = nt*8 + lt*2 + j;
                        if (co < 81) {
                            float e = __expf(v[nt][j] - mx);
                            se += e;
                            int kh = co / 9, kw = co - kh*9;
                            int sy = Y + kh - 4, sx2 = X + kw - 4;
                            float sv = 0.f;
                            if ((unsigned)sy < 256u && (unsigned)sx2 < 256u)
                                sv = sp[sy*256 + sx2];
                            fo += e * sv;
                        }
                    }
                }
                se += __shfl_xor_sync(0xffffffffu, se, 1);
                se += __shfl_xor_sync(0xffffffffu, se, 2);
                fo += __shfl_xor_sync(0xffffffffu, fo, 1);
                fo += __shfl_xor_sync(0xffffffffu, fo, 2);
                if (lt == 0)
                    xy[((size_t)n*2 + sel)*HW + Y*256 + X] = fo / se;
            }
        }
    }
}

// ---------------- conv 3x3, 64 -> 1, reads split-fp16 NHWC ----------------
__global__ __launch_bounds__(64) void conv_out1(
    const __half* __restrict__ ihi, const __half* __restrict__ ilo,
    const float* __restrict__ w, const float* __restrict__ b, float* __restrict__ out)
{
    extern __shared__ char sm[];
    char* sh = sm;
    char* sl = sm + 3*66*144;
    float* sw = (float*)(sm + 2*3*66*144);

    int tid = threadIdx.x;
    int bid = blockIdx.x;                 // 16n x 256y x 4xq
    int xq = bid & 3;
    int y  = (bid >> 2) & 255;
    int n  = bid >> 10;
    int x0 = xq * 64;
    size_t nbase = (size_t)n * 65536;

    for (int idx = tid; idx < 576; idx += 64) sw[idx] = w[idx];
    for (int idx = tid; idx < 3*66*8; idx += 64) {
        int c = idx & 7, e = idx >> 3;
        int row = e / 66, px = e - row*66;
        int gy = y + row - 1, gx = x0 + px - 1;
        uint4 vh = make_uint4(0,0,0,0), vl = vh;
        if ((unsigned)gy < 256u && (unsigned)gx < 256u) {
            size_t pix = nbase + gy*256 + gx;
            vh = *(const uint4*)((const char*)ihi + pix*128 + c*16);
            vl = *(const uint4*)((const char*)ilo + pix*128 + c*16);
        }
        int so = (row*66 + px)*144 + c*16;
        *(uint4*)(sh + so) = vh;
        *(uint4*)(sl + so) = vl;
    }
    __syncthreads();

    float a = b[0];
    #pragma unroll
    for (int kh = 0; kh < 3; kh++)
    #pragma unroll
    for (int kw = 0; kw < 3; kw++) {
        int base = (kh*66 + tid + kw)*144;
        int tap = kh*3 + kw;
        #pragma unroll
        for (int cq = 0; cq < 8; cq++) {
            uint4 H = *(const uint4*)(sh + base + cq*16);
            uint4 L = *(const uint4*)(sl + base + cq*16);
            uint32_t hw[4] = {H.x, H.y, H.z, H.w};
            uint32_t lw[4] = {L.x, L.y, L.z, L.w};
            #pragma unroll
            for (int t = 0; t < 4; t++) {
                float v0 = h2f(hw[t], 0) + h2f(lw[t], 0);
                float v1 = h2f(hw[t], 1) + h2f(lw[t], 1);
                int ci = cq*8 + t*2;
                a += sw[ci*9 + tap] * v0;
                a += sw[(ci+1)*9 + tap] * v1;
            }
        }
    }
    out[nbase + (size_t)y*256 + x0 + tid] = a;
}

// ---------------- launch ----------------
extern "C" void kernel_launch(void* const* d_in, const int* in_sizes, int n_in,
                              void* d_out, int out_size)
{
    const float* x     = (const float*)d_in[0];
    const float* g     = (const float*)d_in[1];
    const float* fx_w1 = (const float*)d_in[2];
    const float* fx_b1 = (const float*)d_in[3];
    const float* fx_w2 = (const float*)d_in[4];
    const float* fx_b2 = (const float*)d_in[5];
    const float* fx_w3 = (const float*)d_in[6];
    const float* fx_b3 = (const float*)d_in[7];
    const float* fg_w1 = (const float*)d_in[8];
    const float* fg_b1 = (const float*)d_in[9];
    const float* fg_w2 = (const float*)d_in[10];
    const float* fg_b2 = (const float*)d_in[11];
    const float* fg_w3 = (const float*)d_in[12];
    const float* fg_b3 = (const float*)d_in[13];
    const float* c1_w  = (const float*)d_in[14];
    const float* c1_b  = (const float*)d_in[15];
    const float* c2_w  = (const float*)d_in[16];
    const float* c2_b  = (const float*)d_in[17];
    const float* c3_w  = (const float*)d_in[18];
    const float* c3_b  = (const float*)d_in[19];
    float* out = (float*)d_out;

    __half *h2h, *h2l;
    float *xy; uint32_t *wq;
    cudaGetSymbolAddress((void**)&h2h, g_h2h);
    cudaGetSymbolAddress((void**)&h2l, g_h2l);
    cudaGetSymbolAddress((void**)&xy, g_xy);
    cudaGetSymbolAddress((void**)&wq, g_wq);

    const int C64_BLOCKS = Nn*128*4;       // 8192
    const int OUT_BLOCKS = Nn*256*4;       // 16384

    const int SMA1 = 78336 + 64*4 + (408 + 576 + 64)*4;       // CIN=1
    const int SMA2 = 78336 + 64*4 + (816 + 1152 + 64)*4;      // CIN=2
    const int SMB  = 78336 + 88*4;                            // CIN=0, NT=11
    const int SMO  = 2*(3*66*144) + 576*4;

    cudaFuncSetAttribute((const void*)conv64m<8, 64, 1, false>,
                         cudaFuncAttributeMaxDynamicSharedMemorySize, SMA1);
    cudaFuncSetAttribute((const void*)conv64m<8, 64, 2, false>,
                         cudaFuncAttributeMaxDynamicSharedMemorySize, SMA2);
    cudaFuncSetAttribute((const void*)conv64m<11, 81, 0, true>,
                         cudaFuncAttributeMaxDynamicSharedMemorySize, SMB);
    cudaFuncSetAttribute((const void*)conv_out1,
                         cudaFuncAttributeMaxDynamicSharedMemorySize, SMO);

    const int PQ64 = (9*4*8*32 + 255)/256;   // 36
    const int PQ88 = (9*4*11*32 + 255)/256;  // 50

    // x head: fused (conv1+conv2) then fused (conv3+softmax+filter)
    prepack_wq<8, 64><<<PQ64, 256>>>(fx_w2, wq);
    conv64m<8, 64, 1, false><<<C64_BLOCKS, 128, SMA1>>>(
        x, fx_w1, fx_b1, nullptr, nullptr, wq, fx_b2, h2h, h2l, nullptr, nullptr, 0);
    prepack_wq<11, 81><<<PQ88, 256>>>(fx_w3, wq);
    conv64m<11, 81, 0, true><<<C64_BLOCKS, 128, SMB>>>(
        nullptr, nullptr, nullptr, h2h, h2l, wq, fx_b3, nullptr, nullptr, x, xy, 0);

    // g head
    prepack_wq<8, 64><<<PQ64, 256>>>(fg_w2, wq);
    conv64m<8, 64, 1, false><<<C64_BLOCKS, 128, SMA1>>>(
        g, fg_w1, fg_b1, nullptr, nullptr, wq, fg_b2, h2h, h2l, nullptr, nullptr, 0);
    prepack_wq<11, 81><<<PQ88, 256>>>(fg_w3, wq);
    conv64m<11, 81, 0, true><<<C64_BLOCKS, 128, SMB>>>(
        nullptr, nullptr, nullptr, h2h, h2l, wq, fg_b3, nullptr, nullptr, g, xy, 1);

    // fusion head: fused (c1+c2), then c3
    prepack_wq<8, 64><<<PQ64, 256>>>(c2_w, wq);
    conv64m<8, 64, 2, false><<<C64_BLOCKS, 128, SMA2>>>(
        xy, c1_w, c1_b, nullptr, nullptr, wq, c2_b, h2h, h2l, nullptr, nullptr, 0);
    conv_out1<<<OUT_BLOCKS, 64, SMO>>>(h2h, h2l, c3_w, c3_b, out);
}

// round 8
// speedup vs baseline: 1.7606x; 1.7606x over previous
#include <cuda_runtime.h>
#include <cuda_fp16.h>
#include <cstdint>
#include <math.h>

#define Nn 16
#define Hh 256
#define Ww 256
#define HW (Hh*Ww)

// ---------------- scratch (device globals; no allocation allowed) ----------------
__device__ __half g_h1h[(size_t)Nn*HW*64];
__device__ __half g_h1l[(size_t)Nn*HW*64];
__device__ __half g_h2h[(size_t)Nn*HW*64];
__device__ __half g_h2l[(size_t)Nn*HW*64];
__device__ float g_xy[(size_t)Nn*2*HW];
__device__ uint32_t g_wq[9*4*11*32*2];   // prepacked B fragments for current conv

__device__ __forceinline__ void hsplit(float v, unsigned short& h, unsigned short& l) {
    __half hb = __float2half_rn(v);
    float hf = __half2float(hb);
    __half lb = __float2half_rn(v - hf);
    h = __half_as_ushort(hb);
    l = __half_as_ushort(lb);
}
__device__ __forceinline__ float h2f(uint32_t u, int hi) {
    return __half2float(__ushort_as_half((unsigned short)(hi ? (u >> 16) : (u & 0xFFFF))));
}
__device__ __forceinline__ void mma_f16(float* c, const uint32_t* a, uint32_t b0, uint32_t b1) {
    asm volatile("mma.sync.aligned.m16n8k16.row.col.f32.f16.f16.f32 "
        "{%0,%1,%2,%3},{%4,%5,%6,%7},{%8,%9},{%0,%1,%2,%3};"
        : "+f"(c[0]), "+f"(c[1]), "+f"(c[2]), "+f"(c[3])
        : "r"(a[0]), "r"(a[1]), "r"(a[2]), "r"(a[3]), "r"(b0), "r"(b1));
}
__device__ __forceinline__ void ldm_x4(uint32_t* r, uint32_t saddr) {
    asm volatile("ldmatrix.sync.aligned.m8n8.x4.shared.b16 {%0,%1,%2,%3}, [%4];"
        : "=r"(r[0]), "=r"(r[1]), "=r"(r[2]), "=r"(r[3]) : "r"(saddr));
}

// ------------- weight prepack: w[co][ci][3][3] fp32 -> B fragments [tap][k][nt][lane][2]u32 ----
template<int NT, int CO>
__global__ void prepack_wq(const float* __restrict__ w, uint32_t* __restrict__ o) {
    int idx = blockIdx.x * 256 + threadIdx.x;
    if (idx >= 9*4*NT*32) return;
    int lane = idx & 31;
    int nt = (idx >> 5) % NT;
    int k  = (idx / (32*NT)) & 3;
    int tap = idx / (32*NT*4);
    int lg = lane >> 2, lt = lane & 3;
    int co = nt*8 + lg;
    auto wv = [&](int ci) -> uint32_t {
        float v = (co < CO) ? w[((size_t)co*64 + ci)*9 + tap] : 0.f;
        return (uint32_t)__half_as_ushort(__float2half_rn(v));
    };
    int c0 = k*16 + lt*2;
    o[idx*2]   = wv(c0)   | (wv(c0+1) << 16);
    o[idx*2+1] = wv(c0+8) | (wv(c0+9) << 16);
}

// ---------------- conv 3x3, small Cin (1 or 2) -> 64 relu, writes split-fp16 NHWC ----------
template<int CIN>
__global__ __launch_bounds__(256) void conv_in_small(
    const float* __restrict__ in, const float* __restrict__ w,
    const float* __restrict__ b, __half* __restrict__ ohi, __half* __restrict__ olo)
{
    __shared__ float s_w[64*CIN*9];
    __shared__ float s_b[64];
    int tid = threadIdx.x;
    for (int i = tid; i < 64*CIN*9; i += 256) s_w[i] = w[i];
    if (tid < 64) s_b[tid] = b[tid];
    __syncthreads();

    int px = blockIdx.x*256 + tid;
    int n = px >> 16; int rem = px & 65535;
    int y = rem >> 8;  int x = rem & 255;

    float iv[CIN*9];
    #pragma unroll
    for (int c = 0; c < CIN; c++)
        #pragma unroll
        for (int kh = 0; kh < 3; kh++)
            #pragma unroll
            for (int kw = 0; kw < 3; kw++) {
                int yy = y + kh - 1, xx = x + kw - 1;
                float v = 0.f;
                if (yy >= 0 && yy < Hh && xx >= 0 && xx < Ww)
                    v = in[((size_t)n*CIN + c)*HW + yy*Ww + xx];
                iv[c*9 + kh*3 + kw] = v;
            }

    float a[64];
    #pragma unroll
    for (int co = 0; co < 64; co++) {
        float s = s_b[co];
        #pragma unroll
        for (int i = 0; i < CIN*9; i++) s += s_w[co*CIN*9 + i] * iv[i];
        a[co] = fmaxf(s, 0.f);
    }

    char* ph = (char*)ohi + (size_t)px * 128;
    char* pl = (char*)olo + (size_t)px * 128;
    #pragma unroll
    for (int q = 0; q < 8; q++) {
        uint32_t hw[4], lw[4];
        #pragma unroll
        for (int t = 0; t < 4; t++) {
            int co = q*8 + t*2;
            unsigned short h0, l0, h1, l1;
            hsplit(a[co], h0, l0); hsplit(a[co+1], h1, l1);
            hw[t] = (uint32_t)h0 | ((uint32_t)h1 << 16);
            lw[t] = (uint32_t)l0 | ((uint32_t)l1 << 16);
        }
        *(uint4*)(ph + q*16) = make_uint4(hw[0], hw[1], hw[2], hw[3]);
        *(uint4*)(pl + q*16) = make_uint4(lw[0], lw[1], lw[2], lw[3]);
    }
}

// ---------------- mma.sync conv 3x3, 64 -> CO, split-fp16 activations, 2-pass -----------
// CTA: 128 thr = 4 warps, M = 128 px (2 y-rows x 64 x). A tile: 4 rows x 66 px x 144B x 2.
// 3 CTAs/SM target. FUSE: fused bias+softmax(81)+9x9 filter epilogue.
template<int NT, int CO, bool FUSE>
__global__ __launch_bounds__(128, 3) void conv64m(
    const __half* __restrict__ ihi, const __half* __restrict__ ilo,
    const uint32_t* __restrict__ wq, const float* __restrict__ bias,
    __half* __restrict__ ohi, __half* __restrict__ olo,
    const float* __restrict__ fsrc, float* __restrict__ xy, int sel)
{
    constexpr int CP = NT * 8;
    constexpr int AH = 4*66*144;          // 38016 bytes per half
    extern __shared__ char sm[];
    char* sAh = sm;
    char* sAl = sm + AH;
    float* s_bias = (float*)(sm + 2*AH);

    int tid = threadIdx.x;
    int lane = tid & 31, wid = tid >> 5;
    int lg = lane >> 2, lt = lane & 3;
    int py = wid >> 1, xb = (wid & 1) * 32;

    int bid = blockIdx.x;                // 16n x 128yp x 4xq
    int xq = bid & 3;
    int yp = (bid >> 2) & 127;
    int n  = bid >> 9;
    int y0 = yp * 2, x0 = xq * 64;
    size_t nbase = (size_t)n * 65536;

    if (tid < CP) s_bias[tid] = (tid < CO) ? bias[tid] : 0.f;

    // stage A tile from split-fp16 global (zero halo = conv zero-padding)
    for (int idx = tid; idx < 4*66*8; idx += 128) {
        int c = idx & 7, e = idx >> 3;
        int row = e / 66, px = e - row*66;
        int gy = y0 + row - 1, gx = x0 + px - 1;
        uint4 vh = make_uint4(0,0,0,0), vl = vh;
        if ((unsigned)gy < 256u && (unsigned)gx < 256u) {
            size_t pix = nbase + gy*256 + gx;
            vh = *(const uint4*)((const char*)ihi + pix*128 + c*16);
            vl = *(const uint4*)((const char*)ilo + pix*128 + c*16);
        }
        int so = (row*66 + px)*144 + c*16;
        *(uint4*)(sAh + so) = vh;
        *(uint4*)(sAl + so) = vl;
    }
    __syncthreads();

    float acc[2][NT][4];
    #pragma unroll
    for (int mt = 0; mt < 2; mt++)
        #pragma unroll
        for (int nt = 0; nt < NT; nt++)
            #pragma unroll
            for (int j = 0; j < 4; j++) acc[mt][nt][j] = 0.f;

    uint32_t sA_s = (uint32_t)__cvta_generic_to_shared(sAh);
    uint32_t rbase = (uint32_t)((lane & 15) * 144 + ((lane >> 4) << 4));

    #pragma unroll 1
    for (int tap = 0; tap < 9; tap++) {
        int kh = tap / 3, kw = tap - kh*3;
        uint32_t base0 = sA_s + (uint32_t)(((py + kh)*66 + xb + kw)*144) + rbase;
        const uint32_t* wt = wq + (size_t)tap*4*NT*64 + lane*2;
        #pragma unroll
        for (int k = 0; k < 4; k++) {
            uint32_t ah[2][4], al[2][4];
            #pragma unroll
            for (int mt = 0; mt < 2; mt++) {
                uint32_t ad = base0 + mt*2304 + k*32;
                ldm_x4(ah[mt], ad);
                ldm_x4(al[mt], ad + AH);
            }
            const uint32_t* wk = wt + (size_t)k*NT*64;
            #pragma unroll
            for (int nt = 0; nt < NT; nt++) {
                uint2 bb = *(const uint2*)(wk + (size_t)nt*64);
                #pragma unroll
                for (int mt = 0; mt < 2; mt++) {
                    mma_f16(acc[mt][nt], ah[mt], bb.x, bb.y);
                    mma_f16(acc[mt][nt], al[mt], bb.x, bb.y);
                }
            }
        }
    }

    if (!FUSE) {
        // bias + relu + split-fp16 global
        #pragma unroll
        for (int mt = 0; mt < 2; mt++) {
            size_t pix0 = nbase + (size_t)(y0 + py)*256 + x0 + xb + mt*16 + lg;
            #pragma unroll
            for (int nt = 0; nt < NT; nt++) {
                int co = nt*8 + lt*2;
                float b0 = s_bias[co], b1v = s_bias[co+1];
                float v00 = fmaxf(acc[mt][nt][0] + b0, 0.f);
                float v01 = fmaxf(acc[mt][nt][1] + b1v, 0.f);
                float v10 = fmaxf(acc[mt][nt][2] + b0, 0.f);
                float v11 = fmaxf(acc[mt][nt][3] + b1v, 0.f);
                unsigned short h0,l0,h1_,l1_;
                hsplit(v00,h0,l0); hsplit(v01,h1_,l1_);
                *(uint32_t*)((char*)ohi + pix0*128 + co*2) = (uint32_t)h0 | ((uint32_t)h1_<<16);
                *(uint32_t*)((char*)olo + pix0*128 + co*2) = (uint32_t)l0 | ((uint32_t)l1_<<16);
                hsplit(v10,h0,l0); hsplit(v11,h1_,l1_);
                *(uint32_t*)((char*)ohi + (pix0+8)*128 + co*2) = (uint32_t)h0 | ((uint32_t)h1_<<16);
                *(uint32_t*)((char*)olo + (pix0+8)*128 + co*2) = (uint32_t)l0 | ((uint32_t)l1_<<16);
            }
        }
    } else {
        // fused softmax over 81 logits + 9x9 pixel-adaptive filtering
        const float* sp = fsrc + nbase;
        int Y = y0 + py;
        #pragma unroll
        for (int mt = 0; mt < 2; mt++) {
            #pragma unroll
            for (int r = 0; r < 2; r++) {
                int X = x0 + xb + mt*16 + lg + r*8;
                float v[NT][2];
                float mx = -1e30f;
                #pragma unroll
                for (int nt = 0; nt < NT; nt++) {
                    #pragma unroll
                    for (int j = 0; j < 2; j++) {
                        int co = nt*8 + lt*2 + j;
                        v[nt][j] = acc[mt][nt][r*2 + j] + s_bias[co];
                        if (co < 81) mx = fmaxf(mx, v[nt][j]);
                    }
                }
                mx = fmaxf(mx, __shfl_xor_sync(0xffffffffu, mx, 1));
                mx = fmaxf(mx, __shfl_xor_sync(0xffffffffu, mx, 2));
                float se = 0.f, fo = 0.f;
                #pragma unroll
                for (int nt = 0; nt < NT; nt++) {
                    #pragma unroll
                    for (int j = 0; j < 2; j++) {
                        int co = nt*8 + lt*2 + j;
                        if (co < 81) {
                            float e = __expf(v[nt][j] - mx);
                            se += e;
                            int kh = co / 9, kw = co - kh*9;
                            int sy = Y + kh - 4, sx2 = X + kw - 4;
                            float sv = 0.f;
                            if ((unsigned)sy < 256u && (unsigned)sx2 < 256u)
                                sv = sp[sy*256 + sx2];
                            fo += e * sv;
                        }
                    }
                }
                se += __shfl_xor_sync(0xffffffffu, se, 1);
                se += __shfl_xor_sync(0xffffffffu, se, 2);
                fo += __shfl_xor_sync(0xffffffffu, fo, 1);
                fo += __shfl_xor_sync(0xffffffffu, fo, 2);
                if (lt == 0)
                    xy[((size_t)n*2 + sel)*HW + Y*256 + X] = fo / se;
            }
        }
    }
}

// ---------------- conv 3x3, 64 -> 1, reads split-fp16 NHWC ----------------
__global__ __launch_bounds__(64) void conv_out1(
    const __half* __restrict__ ihi, const __half* __restrict__ ilo,
    const float* __restrict__ w, const float* __restrict__ b, float* __restrict__ out)
{
    extern __shared__ char sm[];
    char* sh = sm;
    char* sl = sm + 3*66*144;
    float* sw = (float*)(sm + 2*3*66*144);

    int tid = threadIdx.x;
    int bid = blockIdx.x;                 // 16n x 256y x 4xq
    int xq = bid & 3;
    int y  = (bid >> 2) & 255;
    int n  = bid >> 10;
    int x0 = xq * 64;
    size_t nbase = (size_t)n * 65536;

    for (int idx = tid; idx < 576; idx += 64) sw[idx] = w[idx];
    for (int idx = tid; idx < 3*66*8; idx += 64) {
        int c = idx & 7, e = idx >> 3;
        int row = e / 66, px = e - row*66;
        int gy = y + row - 1, gx = x0 + px - 1;
        uint4 vh = make_uint4(0,0,0,0), vl = vh;
        if ((unsigned)gy < 256u && (unsigned)gx < 256u) {
            size_t pix = nbase + gy*256 + gx;
            vh = *(const uint4*)((const char*)ihi + pix*128 + c*16);
            vl = *(const uint4*)((const char*)ilo + pix*128 + c*16);
        }
        int so = (row*66 + px)*144 + c*16;
        *(uint4*)(sh + so) = vh;
        *(uint4*)(sl + so) = vl;
    }
    __syncthreads();

    float a = b[0];
    #pragma unroll
    for (int kh = 0; kh < 3; kh++)
    #pragma unroll
    for (int kw = 0; kw < 3; kw++) {
        int base = (kh*66 + tid + kw)*144;
        int tap = kh*3 + kw;
        #pragma unroll
        for (int cq = 0; cq < 8; cq++) {
            uint4 H = *(const uint4*)(sh + base + cq*16);
            uint4 L = *(const uint4*)(sl + base + cq*16);
            uint32_t hw[4] = {H.x, H.y, H.z, H.w};
            uint32_t lw[4] = {L.x, L.y, L.z, L.w};
            #pragma unroll
            for (int t = 0; t < 4; t++) {
                float v0 = h2f(hw[t], 0) + h2f(lw[t], 0);
                float v1 = h2f(hw[t], 1) + h2f(lw[t], 1);
                int ci = cq*8 + t*2;
                a += sw[ci*9 + tap] * v0;
                a += sw[(ci+1)*9 + tap] * v1;
            }
        }
    }
    out[nbase + (size_t)y*256 + x0 + tid] = a;
}

// ---------------- launch ----------------
extern "C" void kernel_launch(void* const* d_in, const int* in_sizes, int n_in,
                              void* d_out, int out_size)
{
    const float* x     = (const float*)d_in[0];
    const float* g     = (const float*)d_in[1];
    const float* fx_w1 = (const float*)d_in[2];
    const float* fx_b1 = (const float*)d_in[3];
    const float* fx_w2 = (const float*)d_in[4];
    const float* fx_b2 = (const float*)d_in[5];
    const float* fx_w3 = (const float*)d_in[6];
    const float* fx_b3 = (const float*)d_in[7];
    const float* fg_w1 = (const float*)d_in[8];
    const float* fg_b1 = (const float*)d_in[9];
    const float* fg_w2 = (const float*)d_in[10];
    const float* fg_b2 = (const float*)d_in[11];
    const float* fg_w3 = (const float*)d_in[12];
    const float* fg_b3 = (const float*)d_in[13];
    const float* c1_w  = (const float*)d_in[14];
    const float* c1_b  = (const float*)d_in[15];
    const float* c2_w  = (const float*)d_in[16];
    const float* c2_b  = (const float*)d_in[17];
    const float* c3_w  = (const float*)d_in[18];
    const float* c3_b  = (const float*)d_in[19];
    float* out = (float*)d_out;

    __half *h1h, *h1l, *h2h, *h2l;
    float *xy; uint32_t *wq;
    cudaGetSymbolAddress((void**)&h1h, g_h1h);
    cudaGetSymbolAddress((void**)&h1l, g_h1l);
    cudaGetSymbolAddress((void**)&h2h, g_h2h);
    cudaGetSymbolAddress((void**)&h2l, g_h2l);
    cudaGetSymbolAddress((void**)&xy, g_xy);
    cudaGetSymbolAddress((void**)&wq, g_wq);

    const int PIX_BLOCKS = Nn*HW/256;      // 65536
    const int C64_BLOCKS = Nn*128*4;       // 8192
    const int OUT_BLOCKS = Nn*256*4;       // 16384

    const int AH = 4*66*144;               // 38016
    const int SM64 = 2*AH + 64*4;          // 76288
    const int SM88 = 2*AH + 88*4;          // 76384
    const int SMO  = 2*(3*66*144) + 576*4; // 59328

    cudaFuncSetAttribute((const void*)conv64m<8, 64, false>,
                         cudaFuncAttributeMaxDynamicSharedMemorySize, SM64);
    cudaFuncSetAttribute((const void*)conv64m<11, 81, true>,
                         cudaFuncAttributeMaxDynamicSharedMemorySize, SM88);
    cudaFuncSetAttribute((const void*)conv_out1,
                         cudaFuncAttributeMaxDynamicSharedMemorySize, SMO);

    const int PQ64 = (9*4*8*32 + 255)/256;   // 36
    const int PQ88 = (9*4*11*32 + 255)/256;  // 50

    // x head
    conv_in_small<1><<<PIX_BLOCKS, 256>>>(x, fx_w1, fx_b1, h1h, h1l);
    prepack_wq<8, 64><<<PQ64, 256>>>(fx_w2, wq);
    conv64m<8, 64, false><<<C64_BLOCKS, 128, SM64>>>(h1h, h1l, wq, fx_b2, h2h, h2l, nullptr, nullptr, 0);
    prepack_wq<11, 81><<<PQ88, 256>>>(fx_w3, wq);
    conv64m<11, 81, true><<<C64_BLOCKS, 128, SM88>>>(h2h, h2l, wq, fx_b3, nullptr, nullptr, x, xy, 0);

    // g head
    conv_in_small<1><<<PIX_BLOCKS, 256>>>(g, fg_w1, fg_b1, h1h, h1l);
    prepack_wq<8, 64><<<PQ64, 256>>>(fg_w2, wq);
    conv64m<8, 64, false><<<C64_BLOCKS, 128, SM64>>>(h1h, h1l, wq, fg_b2, h2h, h2l, nullptr, nullptr, 0);
    prepack_wq<11, 81><<<PQ88, 256>>>(fg_w3, wq);
    conv64m<11, 81, true><<<C64_BLOCKS, 128, SM88>>>(h2h, h2l, wq, fg_b3, nullptr, nullptr, g, xy, 1);

    // fusion head
    conv_in_small<2><<<PIX_BLOCKS, 256>>>(xy, c1_w, c1_b, h1h, h1l);
    prepack_wq<8, 64><<<PQ64, 256>>>(c2_w, wq);
    conv64m<8, 64, false><<<C64_BLOCKS, 128, SM64>>>(h1h, h1l, wq, c2_b, h2h, h2l, nullptr, nullptr, 0);
    conv_out1<<<OUT_BLOCKS, 64, SMO>>>(h2h, h2l, c3_w, c3_b, out);
}

// round 9
// speedup vs baseline: 2.7057x; 1.5368x over previous
#include <cuda_runtime.h>
#include <cuda_fp16.h>
#include <cstdint>
#include <math.h>

#define Nn 16
#define Hh 256
#define Ww 256
#define HW (Hh*Ww)

// ---------------- scratch (device globals; no allocation allowed) ----------------
__device__ __half g_h1[(size_t)Nn*HW*64];
__device__ __half g_h2[(size_t)Nn*HW*64];
__device__ float g_xy[(size_t)Nn*2*HW];
__device__ uint32_t g_wq[9*4*11*32*2];   // prepacked B fragments for current conv

__device__ __forceinline__ float h2f(uint32_t u, int hi) {
    return __half2float(__ushort_as_half((unsigned short)(hi ? (u >> 16) : (u & 0xFFFF))));
}
__device__ __forceinline__ void mma_f16(float* c, const uint32_t* a, uint32_t b0, uint32_t b1) {
    asm volatile("mma.sync.aligned.m16n8k16.row.col.f32.f16.f16.f32 "
        "{%0,%1,%2,%3},{%4,%5,%6,%7},{%8,%9},{%0,%1,%2,%3};"
        : "+f"(c[0]), "+f"(c[1]), "+f"(c[2]), "+f"(c[3])
        : "r"(a[0]), "r"(a[1]), "r"(a[2]), "r"(a[3]), "r"(b0), "r"(b1));
}
__device__ __forceinline__ void ldm_x4(uint32_t* r, uint32_t saddr) {
    asm volatile("ldmatrix.sync.aligned.m8n8.x4.shared.b16 {%0,%1,%2,%3}, [%4];"
        : "=r"(r[0]), "=r"(r[1]), "=r"(r[2]), "=r"(r[3]) : "r"(saddr));
}
__device__ __forceinline__ uint32_t pkh2(float a, float b) {
    return (uint32_t)__half_as_ushort(__float2half_rn(a)) |
           ((uint32_t)__half_as_ushort(__float2half_rn(b)) << 16);
}

// ------------- weight prepack: w[co][ci][3][3] fp32 -> B fragments [tap][k][nt][lane][2]u32 ----
template<int NT, int CO>
__global__ void prepack_wq(const float* __restrict__ w, uint32_t* __restrict__ o) {
    int idx = blockIdx.x * 256 + threadIdx.x;
    if (idx >= 9*4*NT*32) return;
    int lane = idx & 31;
    int nt = (idx >> 5) % NT;
    int k  = (idx / (32*NT)) & 3;
    int tap = idx / (32*NT*4);
    int lg = lane >> 2, lt = lane & 3;
    int co = nt*8 + lg;
    auto wv = [&](int ci) -> uint32_t {
        float v = (co < CO) ? w[((size_t)co*64 + ci)*9 + tap] : 0.f;
        return (uint32_t)__half_as_ushort(__float2half_rn(v));
    };
    int c0 = k*16 + lt*2;
    o[idx*2]   = wv(c0)   | (wv(c0+1) << 16);
    o[idx*2+1] = wv(c0+8) | (wv(c0+9) << 16);
}

// ---------------- conv 3x3, small Cin (1 or 2) -> 64 relu, writes fp16 NHWC ----------
template<int CIN>
__global__ __launch_bounds__(256) void conv_in_small(
    const float* __restrict__ in, const float* __restrict__ w,
    const float* __restrict__ b, __half* __restrict__ oh)
{
    __shared__ float s_w[64*CIN*9];
    __shared__ float s_b[64];
    int tid = threadIdx.x;
    for (int i = tid; i < 64*CIN*9; i += 256) s_w[i] = w[i];
    if (tid < 64) s_b[tid] = b[tid];
    __syncthreads();

    int px = blockIdx.x*256 + tid;
    int n = px >> 16; int rem = px & 65535;
    int y = rem >> 8;  int x = rem & 255;

    float iv[CIN*9];
    #pragma unroll
    for (int c = 0; c < CIN; c++)
        #pragma unroll
        for (int kh = 0; kh < 3; kh++)
            #pragma unroll
            for (int kw = 0; kw < 3; kw++) {
                int yy = y + kh - 1, xx = x + kw - 1;
                float v = 0.f;
                if (yy >= 0 && yy < Hh && xx >= 0 && xx < Ww)
                    v = in[((size_t)n*CIN + c)*HW + yy*Ww + xx];
                iv[c*9 + kh*3 + kw] = v;
            }

    float a[64];
    #pragma unroll
    for (int co = 0; co < 64; co++) {
        float s = s_b[co];
        #pragma unroll
        for (int i = 0; i < CIN*9; i++) s += s_w[co*CIN*9 + i] * iv[i];
        a[co] = fmaxf(s, 0.f);
    }

    char* ph = (char*)oh + (size_t)px * 128;
    #pragma unroll
    for (int q = 0; q < 8; q++) {
        uint32_t hw[4];
        #pragma unroll
        for (int t = 0; t < 4; t++)
            hw[t] = pkh2(a[q*8 + t*2], a[q*8 + t*2 + 1]);
        *(uint4*)(ph + q*16) = make_uint4(hw[0], hw[1], hw[2], hw[3]);
    }
}

// ---------------- mma.sync conv 3x3, 64 -> CO, fp16 activations, single pass ----------
// CTA: 128 thr = 4 warps, M = 128 px (2 y-rows x 64 x). A tile: 4 rows x 66 px x 144B.
// FUSE: fused bias+softmax(81)+9x9 filter epilogue.
template<int NT, int CO, bool FUSE>
__global__ __launch_bounds__(128, (NT == 8) ? 4 : 3) void conv64m(
    const __half* __restrict__ ih,
    const uint32_t* __restrict__ wq, const float* __restrict__ bias,
    __half* __restrict__ oh,
    const float* __restrict__ fsrc, float* __restrict__ xy, int sel)
{
    constexpr int CP = NT * 8;
    constexpr int AH = 4*66*144;          // 38016 bytes
    extern __shared__ char sm[];
    char* sA = sm;
    float* s_bias = (float*)(sm + AH);

    int tid = threadIdx.x;
    int lane = tid & 31, wid = tid >> 5;
    int lg = lane >> 2, lt = lane & 3;
    int py = wid >> 1, xb = (wid & 1) * 32;

    int bid = blockIdx.x;                // 16n x 128yp x 4xq
    int xq = bid & 3;
    int yp = (bid >> 2) & 127;
    int n  = bid >> 9;
    int y0 = yp * 2, x0 = xq * 64;
    size_t nbase = (size_t)n * 65536;

    if (tid < CP) s_bias[tid] = (tid < CO) ? bias[tid] : 0.f;

    // stage A tile from fp16 global (zero halo = conv zero-padding)
    for (int idx = tid; idx < 4*66*8; idx += 128) {
        int c = idx & 7, e = idx >> 3;
        int row = e / 66, px = e - row*66;
        int gy = y0 + row - 1, gx = x0 + px - 1;
        uint4 vh = make_uint4(0,0,0,0);
        if ((unsigned)gy < 256u && (unsigned)gx < 256u)
            vh = *(const uint4*)((const char*)ih + (nbase + gy*256 + gx)*128 + c*16);
        *(uint4*)(sA + (row*66 + px)*144 + c*16) = vh;
    }
    __syncthreads();

    float acc[2][NT][4];
    #pragma unroll
    for (int mt = 0; mt < 2; mt++)
        #pragma unroll
        for (int nt = 0; nt < NT; nt++)
            #pragma unroll
            for (int j = 0; j < 4; j++) acc[mt][nt][j] = 0.f;

    uint32_t sA_s = (uint32_t)__cvta_generic_to_shared(sA);
    uint32_t rbase = (uint32_t)((lane & 15) * 144 + ((lane >> 4) << 4));

    #pragma unroll 1
    for (int tap = 0; tap < 9; tap++) {
        int kh = tap / 3, kw = tap - kh*3;
        uint32_t base0 = sA_s + (uint32_t)(((py + kh)*66 + xb + kw)*144) + rbase;
        const uint32_t* wt = wq + (size_t)tap*4*NT*64 + lane*2;
        #pragma unroll
        for (int k = 0; k < 4; k++) {
            uint32_t ah[2][4];
            #pragma unroll
            for (int mt = 0; mt < 2; mt++)
                ldm_x4(ah[mt], base0 + mt*2304 + k*32);
            const uint32_t* wk = wt + (size_t)k*NT*64;
            #pragma unroll
            for (int nt = 0; nt < NT; nt++) {
                uint2 bb = *(const uint2*)(wk + (size_t)nt*64);
                #pragma unroll
                for (int mt = 0; mt < 2; mt++)
                    mma_f16(acc[mt][nt], ah[mt], bb.x, bb.y);
            }
        }
    }

    if (!FUSE) {
        // bias + relu + fp16 global
        #pragma unroll
        for (int mt = 0; mt < 2; mt++) {
            size_t pix0 = nbase + (size_t)(y0 + py)*256 + x0 + xb + mt*16 + lg;
            #pragma unroll
            for (int nt = 0; nt < NT; nt++) {
                int co = nt*8 + lt*2;
                float b0 = s_bias[co], b1v = s_bias[co+1];
                *(uint32_t*)((char*)oh + pix0*128 + co*2) =
                    pkh2(fmaxf(acc[mt][nt][0] + b0, 0.f), fmaxf(acc[mt][nt][1] + b1v, 0.f));
                *(uint32_t*)((char*)oh + (pix0+8)*128 + co*2) =
                    pkh2(fmaxf(acc[mt][nt][2] + b0, 0.f), fmaxf(acc[mt][nt][3] + b1v, 0.f));
            }
        }
    } else {
        // fused softmax over 81 logits + 9x9 pixel-adaptive filtering
        const float* sp = fsrc + nbase;
        int Y = y0 + py;
        #pragma unroll
        for (int mt = 0; mt < 2; mt++) {
            #pragma unroll
            for (int r = 0; r < 2; r++) {
                int X = x0 + xb + mt*16 + lg + r*8;
                float v[NT][2];
                float mx = -1e30f;
                #pragma unroll
                for (int nt = 0; nt < NT; nt++) {
                    #pragma unroll
                    for (int j = 0; j < 2; j++) {
                        int co = nt*8 + lt*2 + j;
                        v[nt][j] = acc[mt][nt][r*2 + j] + s_bias[co];
                        if (co < 81) mx = fmaxf(mx, v[nt][j]);
                    }
                }
                mx = fmaxf(mx, __shfl_xor_sync(0xffffffffu, mx, 1));
                mx = fmaxf(mx, __shfl_xor_sync(0xffffffffu, mx, 2));
                float se = 0.f, fo = 0.f;
                #pragma unroll
                for (int nt = 0; nt < NT; nt++) {
                    #pragma unroll
                    for (int j = 0; j < 2; j++) {
                        int co = nt*8 + lt*2 + j;
                        if (co < 81) {
                            float e = __expf(v[nt][j] - mx);
                            se += e;
                            int kh = co / 9, kw = co - kh*9;
                            int sy = Y + kh - 4, sx2 = X + kw - 4;
                            float sv = 0.f;
                            if ((unsigned)sy < 256u && (unsigned)sx2 < 256u)
                                sv = sp[sy*256 + sx2];
                            fo += e * sv;
                        }
                    }
                }
                se += __shfl_xor_sync(0xffffffffu, se, 1);
                se += __shfl_xor_sync(0xffffffffu, se, 2);
                fo += __shfl_xor_sync(0xffffffffu, fo, 1);
                fo += __shfl_xor_sync(0xffffffffu, fo, 2);
                if (lt == 0)
                    xy[((size_t)n*2 + sel)*HW + Y*256 + X] = fo / se;
            }
        }
    }
}

// ---------------- conv 3x3, 64 -> 1, reads fp16 NHWC ----------------
__global__ __launch_bounds__(64) void conv_out1(
    const __half* __restrict__ ih,
    const float* __restrict__ w, const float* __restrict__ b, float* __restrict__ out)
{
    extern __shared__ char sm[];
    char* sh = sm;
    float* sw = (float*)(sm + 3*66*144);

    int tid = threadIdx.x;
    int bid = blockIdx.x;                 // 16n x 256y x 4xq
    int xq = bid & 3;
    int y  = (bid >> 2) & 255;
    int n  = bid >> 10;
    int x0 = xq * 64;
    size_t nbase = (size_t)n * 65536;

    for (int idx = tid; idx < 576; idx += 64) sw[idx] = w[idx];
    for (int idx = tid; idx < 3*66*8; idx += 64) {
        int c = idx & 7, e = idx >> 3;
        int row = e / 66, px = e - row*66;
        int gy = y + row - 1, gx = x0 + px - 1;
        uint4 vh = make_uint4(0,0,0,0);
        if ((unsigned)gy < 256u && (unsigned)gx < 256u)
            vh = *(const uint4*)((const char*)ih + (nbase + gy*256 + gx)*128 + c*16);
        *(uint4*)(sh + (row*66 + px)*144 + c*16) = vh;
    }
    __syncthreads();

    float a = b[0];
    #pragma unroll
    for (int kh = 0; kh < 3; kh++)
    #pragma unroll
    for (int kw = 0; kw < 3; kw++) {
        int base = (kh*66 + tid + kw)*144;
        int tap = kh*3 + kw;
        #pragma unroll
        for (int cq = 0; cq < 8; cq++) {
            uint4 H = *(const uint4*)(sh + base + cq*16);
            uint32_t hw[4] = {H.x, H.y, H.z, H.w};
            #pragma unroll
            for (int t = 0; t < 4; t++) {
                int ci = cq*8 + t*2;
                a += sw[ci*9 + tap] * h2f(hw[t], 0);
                a += sw[(ci+1)*9 + tap] * h2f(hw[t], 1);
            }
        }
    }
    out[nbase + (size_t)y*256 + x0 + tid] = a;
}

// ---------------- launch ----------------
extern "C" void kernel_launch(void* const* d_in, const int* in_sizes, int n_in,
                              void* d_out, int out_size)
{
    const float* x     = (const float*)d_in[0];
    const float* g     = (const float*)d_in[1];
    const float* fx_w1 = (const float*)d_in[2];
    const float* fx_b1 = (const float*)d_in[3];
    const float* fx_w2 = (const float*)d_in[4];
    const float* fx_b2 = (const float*)d_in[5];
    const float* fx_w3 = (const float*)d_in[6];
    const float* fx_b3 = (const float*)d_in[7];
    const float* fg_w1 = (const float*)d_in[8];
    const float* fg_b1 = (const float*)d_in[9];
    const float* fg_w2 = (const float*)d_in[10];
    const float* fg_b2 = (const float*)d_in[11];
    const float* fg_w3 = (const float*)d_in[12];
    const float* fg_b3 = (const float*)d_in[13];
    const float* c1_w  = (const float*)d_in[14];
    const float* c1_b  = (const float*)d_in[15];
    const float* c2_w  = (const float*)d_in[16];
    const float* c2_b  = (const float*)d_in[17];
    const float* c3_w  = (const float*)d_in[18];
    const float* c3_b  = (const float*)d_in[19];
    float* out = (float*)d_out;

    __half *h1, *h2;
    float *xy; uint32_t *wq;
    cudaGetSymbolAddress((void**)&h1, g_h1);
    cudaGetSymbolAddress((void**)&h2, g_h2);
    cudaGetSymbolAddress((void**)&xy, g_xy);
    cudaGetSymbolAddress((void**)&wq, g_wq);

    const int PIX_BLOCKS = Nn*HW/256;      // 65536
    const int C64_BLOCKS = Nn*128*4;       // 8192
    const int OUT_BLOCKS = Nn*256*4;       // 16384

    const int AH = 4*66*144;               // 38016
    const int SM64 = AH + 64*4;            // 38272
    const int SM88 = AH + 88*4;            // 38368
    const int SMO  = 3*66*144 + 576*4;     // 30816

    cudaFuncSetAttribute((const void*)conv64m<8, 64, false>,
                         cudaFuncAttributeMaxDynamicSharedMemorySize, SM64);
    cudaFuncSetAttribute((const void*)conv64m<11, 81, true>,
                         cudaFuncAttributeMaxDynamicSharedMemorySize, SM88);
    cudaFuncSetAttribute((const void*)conv_out1,
                         cudaFuncAttributeMaxDynamicSharedMemorySize, SMO);

    const int PQ64 = (9*4*8*32 + 255)/256;   // 36
    const int PQ88 = (9*4*11*32 + 255)/256;  // 50

    // x head
    conv_in_small<1><<<PIX_BLOCKS, 256>>>(x, fx_w1, fx_b1, h1);
    prepack_wq<8, 64><<<PQ64, 256>>>(fx_w2, wq);
    conv64m<8, 64, false><<<C64_BLOCKS, 128, SM64>>>(h1, wq, fx_b2, h2, nullptr, nullptr, 0);
    prepack_wq<11, 81><<<PQ88, 256>>>(fx_w3, wq);
    conv64m<11, 81, true><<<C64_BLOCKS, 128, SM88>>>(h2, wq, fx_b3, nullptr, x, xy, 0);

    // g head
    conv_in_small<1><<<PIX_BLOCKS, 256>>>(g, fg_w1, fg_b1, h1);
    prepack_wq<8, 64><<<PQ64, 256>>>(fg_w2, wq);
    conv64m<8, 64, false><<<C64_BLOCKS, 128, SM64>>>(h1, wq, fg_b2, h2, nullptr, nullptr, 0);
    prepack_wq<11, 81><<<PQ88, 256>>>(fg_w3, wq);
    conv64m<11, 81, true><<<C64_BLOCKS, 128, SM88>>>(h2, wq, fg_b3, nullptr, g, xy, 1);

    // fusion head
    conv_in_small<2><<<PIX_BLOCKS, 256>>>(xy, c1_w, c1_b, h1);
    prepack_wq<8, 64><<<PQ64, 256>>>(c2_w, wq);
    conv64m<8, 64, false><<<C64_BLOCKS, 128, SM64>>>(h1, wq, c2_b, h2, nullptr, nullptr, 0);
    conv_out1<<<OUT_BLOCKS, 64, SMO>>>(h2, c3_w, c3_b, out);
}

// round 11
// speedup vs baseline: 2.7552x; 1.0183x over previous
#include <cuda_runtime.h>
#include <cuda_fp16.h>
#include <cstdint>
#include <math.h>

#define Nn 16
#define Hh 256
#define Ww 256
#define HW (Hh*Ww)

// ---------------- scratch (device globals; no allocation allowed) ----------------
__device__ __half g_h1x[(size_t)Nn*HW*64];
__device__ __half g_h1g[(size_t)Nn*HW*64];
__device__ __half g_h2x[(size_t)Nn*HW*64];
__device__ __half g_h2g[(size_t)Nn*HW*64];
__device__ float g_xy[(size_t)Nn*2*HW];
__device__ uint32_t g_wq8[3][9*4*8*32*2];    // fx2, fg2, c2
__device__ uint32_t g_wq11[2][9*4*11*32*2];  // fx3, fg3

__device__ __forceinline__ float h2f(uint32_t u, int hi) {
    return __half2float(__ushort_as_half((unsigned short)(hi ? (u >> 16) : (u & 0xFFFF))));
}
__device__ __forceinline__ void mma_f16(float* c, const uint32_t* a, uint32_t b0, uint32_t b1) {
    asm volatile("mma.sync.aligned.m16n8k16.row.col.f32.f16.f16.f32 "
        "{%0,%1,%2,%3},{%4,%5,%6,%7},{%8,%9},{%0,%1,%2,%3};"
        : "+f"(c[0]), "+f"(c[1]), "+f"(c[2]), "+f"(c[3])
        : "r"(a[0]), "r"(a[1]), "r"(a[2]), "r"(a[3]), "r"(b0), "r"(b1));
}
__device__ __forceinline__ void ldm_x4(uint32_t* r, uint32_t saddr) {
    asm volatile("ldmatrix.sync.aligned.m8n8.x4.shared.b16 {%0,%1,%2,%3}, [%4];"
        : "=r"(r[0]), "=r"(r[1]), "=r"(r[2]), "=r"(r[3]) : "r"(saddr));
}
__device__ __forceinline__ uint32_t pkh2(float a, float b) {
    return (uint32_t)__half_as_ushort(__float2half_rn(a)) |
           ((uint32_t)__half_as_ushort(__float2half_rn(b)) << 16);
}

// ------------- weight prepack: w[co][ci][3][3] fp32 -> B fragments [tap][k][nt][lane][2]u32 ----
template<int NT, int CO>
__global__ void prepack_wq(const float* __restrict__ w, uint32_t* __restrict__ o) {
    int idx = blockIdx.x * 256 + threadIdx.x;
    if (idx >= 9*4*NT*32) return;
    int lane = idx & 31;
    int nt = (idx >> 5) % NT;
    int k  = (idx / (32*NT)) & 3;
    int tap = idx / (32*NT*4);
    int lg = lane >> 2, lt = lane & 3;
    int co = nt*8 + lg;
    auto wv = [&](int ci) -> uint32_t {
        float v = (co < CO) ? w[((size_t)co*64 + ci)*9 + tap] : 0.f;
        return (uint32_t)__half_as_ushort(__float2half_rn(v));
    };
    int c0 = k*16 + lt*2;
    o[idx*2]   = wv(c0)   | (wv(c0+1) << 16);
    o[idx*2+1] = wv(c0+8) | (wv(c0+9) << 16);
}

// ---------------- conv 3x3, small Cin -> 64 relu, writes fp16 NHWC. Optional 2 heads. ----
// PIX_BLOCKS per head = Nn*HW/256 = 4096 = 2^12.
template<int CIN, bool DUAL>
__global__ __launch_bounds__(256) void conv_in_small(
    const float* __restrict__ in0, const float* __restrict__ w0, const float* __restrict__ b0,
    __half* __restrict__ oh0,
    const float* __restrict__ in1, const float* __restrict__ w1, const float* __restrict__ b1,
    __half* __restrict__ oh1)
{
    __shared__ float s_w[64*CIN*9];
    __shared__ float s_b[64];
    int tid = threadIdx.x;
    int head = DUAL ? (int)(blockIdx.x >> 12) : 0;
    const float* in = head ? in1 : in0;
    const float* w  = head ? w1 : w0;
    const float* b  = head ? b1 : b0;
    __half* oh      = head ? oh1 : oh0;

    for (int i = tid; i < 64*CIN*9; i += 256) s_w[i] = w[i];
    if (tid < 64) s_b[tid] = b[tid];
    __syncthreads();

    int px = (DUAL ? (int)(blockIdx.x & 4095) : (int)blockIdx.x)*256 + tid;
    int n = px >> 16; int rem = px & 65535;
    int y = rem >> 8;  int x = rem & 255;

    float iv[CIN*9];
    #pragma unroll
    for (int c = 0; c < CIN; c++)
        #pragma unroll
        for (int kh = 0; kh < 3; kh++)
            #pragma unroll
            for (int kw = 0; kw < 3; kw++) {
                int yy = y + kh - 1, xx = x + kw - 1;
                float v = 0.f;
                if (yy >= 0 && yy < Hh && xx >= 0 && xx < Ww)
                    v = in[((size_t)n*CIN + c)*HW + yy*Ww + xx];
                iv[c*9 + kh*3 + kw] = v;
            }

    float a[64];
    #pragma unroll
    for (int co = 0; co < 64; co++) {
        float s = s_b[co];
        #pragma unroll
        for (int i = 0; i < CIN*9; i++) s += s_w[co*CIN*9 + i] * iv[i];
        a[co] = fmaxf(s, 0.f);
    }

    char* ph = (char*)oh + (size_t)px * 128;
    #pragma unroll
    for (int q = 0; q < 8; q++) {
        uint32_t hw[4];
        #pragma unroll
        for (int t = 0; t < 4; t++)
            hw[t] = pkh2(a[q*8 + t*2], a[q*8 + t*2 + 1]);
        *(uint4*)(ph + q*16) = make_uint4(hw[0], hw[1], hw[2], hw[3]);
    }
}

// ---------------- mma.sync conv 3x3, 64 -> CO, fp16, single pass. Optional 2 heads. -----
// C64_BLOCKS per head = 8192 = 2^13.
template<int NT, int CO, bool FUSE, bool DUAL>
__global__ __launch_bounds__(128, (NT == 8) ? 4 : 3) void conv64m(
    const __half* __restrict__ ih0, const uint32_t* __restrict__ wq0,
    const float* __restrict__ bias0, __half* __restrict__ oh0, const float* __restrict__ fsrc0,
    const __half* __restrict__ ih1, const uint32_t* __restrict__ wq1,
    const float* __restrict__ bias1, __half* __restrict__ oh1, const float* __restrict__ fsrc1,
    float* __restrict__ xy)
{
    constexpr int CP = NT * 8;
    constexpr int AH = 4*66*144;          // 38016 bytes
    extern __shared__ char sm[];
    char* sA = sm;
    float* s_bias = (float*)(sm + AH);

    int tid = threadIdx.x;
    int lane = tid & 31, wid = tid >> 5;
    int lg = lane >> 2, lt = lane & 3;
    int py = wid >> 1, xb = (wid & 1) * 32;

    int bid = blockIdx.x;
    int head = DUAL ? (bid >> 13) : 0;
    bid &= 8191;                          // 16n x 128yp x 4xq
    const __half* ih = head ? ih1 : ih0;
    const uint32_t* wq = head ? wq1 : wq0;
    const float* bias = head ? bias1 : bias0;
    __half* oh = head ? oh1 : oh0;
    const float* fsrc = head ? fsrc1 : fsrc0;

    int xq = bid & 3;
    int yp = (bid >> 2) & 127;
    int n  = bid >> 9;
    int y0 = yp * 2, x0 = xq * 64;
    size_t nbase = (size_t)n * 65536;

    if (tid < CP) s_bias[tid] = (tid < CO) ? bias[tid] : 0.f;

    // stage A tile from fp16 global (zero halo = conv zero-padding)
    for (int idx = tid; idx < 4*66*8; idx += 128) {
        int c = idx & 7, e = idx >> 3;
        int row = e / 66, px = e - row*66;
        int gy = y0 + row - 1, gx = x0 + px - 1;
        uint4 vh = make_uint4(0,0,0,0);
        if ((unsigned)gy < 256u && (unsigned)gx < 256u)
            vh = *(const uint4*)((const char*)ih + (nbase + gy*256 + gx)*128 + c*16);
        *(uint4*)(sA + (row*66 + px)*144 + c*16) = vh;
    }
    __syncthreads();

    float acc[2][NT][4];
    #pragma unroll
    for (int mt = 0; mt < 2; mt++)
        #pragma unroll
        for (int nt = 0; nt < NT; nt++)
            #pragma unroll
            for (int j = 0; j < 4; j++) acc[mt][nt][j] = 0.f;

    uint32_t sA_s = (uint32_t)__cvta_generic_to_shared(sA);
    uint32_t rbase = (uint32_t)((lane & 15) * 144 + ((lane >> 4) << 4));

    #pragma unroll 1
    for (int tap = 0; tap < 9; tap++) {
        int kh = tap / 3, kw = tap - kh*3;
        uint32_t base0 = sA_s + (uint32_t)(((py + kh)*66 + xb + kw)*144) + rbase;
        const uint32_t* wt = wq + (size_t)tap*4*NT*64 + lane*2;
        #pragma unroll
        for (int k = 0; k < 4; k++) {
            uint32_t ah[2][4];
            #pragma unroll
            for (int mt = 0; mt < 2; mt++)
                ldm_x4(ah[mt], base0 + mt*2304 + k*32);
            const uint32_t* wk = wt + (size_t)k*NT*64;
            #pragma unroll
            for (int nt = 0; nt < NT; nt++) {
                uint2 bb = *(const uint2*)(wk + (size_t)nt*64);
                #pragma unroll
                for (int mt = 0; mt < 2; mt++)
                    mma_f16(acc[mt][nt], ah[mt], bb.x, bb.y);
            }
        }
    }

    if (!FUSE) {
        // bias + relu + fp16 global
        #pragma unroll
        for (int mt = 0; mt < 2; mt++) {
            size_t pix0 = nbase + (size_t)(y0 + py)*256 + x0 + xb + mt*16 + lg;
            #pragma unroll
            for (int nt = 0; nt < NT; nt++) {
                int co = nt*8 + lt*2;
                float b0 = s_bias[co], b1v = s_bias[co+1];
                *(uint32_t*)((char*)oh + pix0*128 + co*2) =
                    pkh2(fmaxf(acc[mt][nt][0] + b0, 0.f), fmaxf(acc[mt][nt][1] + b1v, 0.f));
                *(uint32_t*)((char*)oh + (pix0+8)*128 + co*2) =
                    pkh2(fmaxf(acc[mt][nt][2] + b0, 0.f), fmaxf(acc[mt][nt][3] + b1v, 0.f));
            }
        }
    } else {
        // fused softmax over 81 logits + 9x9 pixel-adaptive filtering
        const float* sp = fsrc + nbase;
        int Y = y0 + py;
        #pragma unroll
        for (int mt = 0; mt < 2; mt++) {
            #pragma unroll
            for (int r = 0; r < 2; r++) {
                int X = x0 + xb + mt*16 + lg + r*8;
                float v[NT][2];
                float mx = -1e30f;
                #pragma unroll
                for (int nt = 0; nt < NT; nt++) {
                    #pragma unroll
                    for (int j = 0; j < 2; j++) {
                        int co = nt*8 + lt*2 + j;
                        v[nt][j] = acc[mt][nt][r*2 + j] + s_bias[co];
                        if (co < 81) mx = fmaxf(mx, v[nt][j]);
                    }
                }
                mx = fmaxf(mx, __shfl_xor_sync(0xffffffffu, mx, 1));
                mx = fmaxf(mx, __shfl_xor_sync(0xffffffffu, mx, 2));
                float se = 0.f, fo = 0.f;
                #pragma unroll
                for (int nt = 0; nt < NT; nt++) {
                    #pragma unroll
                    for (int j = 0; j < 2; j++) {
                        int co = nt*8 + lt*2 + j;
                        if (co < 81) {
                            float e = __expf(v[nt][j] - mx);
                            se += e;
                            int kh = co / 9, kw = co - kh*9;
                            int sy = Y + kh - 4, sx2 = X + kw - 4;
                            float sv = 0.f;
                            if ((unsigned)sy < 256u && (unsigned)sx2 < 256u)
                                sv = sp[sy*256 + sx2];
                            fo += e * sv;
                        }
                    }
                }
                se += __shfl_xor_sync(0xffffffffu, se, 1);
                se += __shfl_xor_sync(0xffffffffu, se, 2);
                fo += __shfl_xor_sync(0xffffffffu, fo, 1);
                fo += __shfl_xor_sync(0xffffffffu, fo, 2);
                if (lt == 0)
                    xy[((size_t)n*2 + head)*HW + Y*256 + X] = fo / se;
            }
        }
    }
}

// ---------------- conv 3x3, 64 -> 1, reads fp16 NHWC ----------------
__global__ __launch_bounds__(64) void conv_out1(
    const __half* __restrict__ ih,
    const float* __restrict__ w, const float* __restrict__ b, float* __restrict__ out)
{
    extern __shared__ char sm[];
    char* sh = sm;
    float* sw = (float*)(sm + 3*66*144);

    int tid = threadIdx.x;
    int bid = blockIdx.x;                 // 16n x 256y x 4xq
    int xq = bid & 3;
    int y  = (bid >> 2) & 255;
    int n  = bid >> 10;
    int x0 = xq * 64;
    size_t nbase = (size_t)n * 65536;

    for (int idx = tid; idx < 576; idx += 64) sw[idx] = w[idx];
    for (int idx = tid; idx < 3*66*8; idx += 64) {
        int c = idx & 7, e = idx >> 3;
        int row = e / 66, px = e - row*66;
        int gy = y + row - 1, gx = x0 + px - 1;
        uint4 vh = make_uint4(0,0,0,0);
        if ((unsigned)gy < 256u && (unsigned)gx < 256u)
            vh = *(const uint4*)((const char*)ih + (nbase + gy*256 + gx)*128 + c*16);
        *(uint4*)(sh + (row*66 + px)*144 + c*16) = vh;
    }
    __syncthreads();

    float a = b[0];
    #pragma unroll
    for (int kh = 0; kh < 3; kh++)
    #pragma unroll
    for (int kw = 0; kw < 3; kw++) {
        int base = (kh*66 + tid + kw)*144;
        int tap = kh*3 + kw;
        #pragma unroll
        for (int cq = 0; cq < 8; cq++) {
            uint4 H = *(const uint4*)(sh + base + cq*16);
            uint32_t hw[4] = {H.x, H.y, H.z, H.w};
            #pragma unroll
            for (int t = 0; t < 4; t++) {
                int ci = cq*8 + t*2;
                a += sw[ci*9 + tap] * h2f(hw[t], 0);
                a += sw[(ci+1)*9 + tap] * h2f(hw[t], 1);
            }
        }
    }
    out[nbase + (size_t)y*256 + x0 + tid] = a;
}

// ---------------- launch ----------------
extern "C" void kernel_launch(void* const* d_in, const int* in_sizes, int n_in,
                              void* d_out, int out_size)
{
    const float* x     = (const float*)d_in[0];
    const float* g     = (const float*)d_in[1];
    const float* fx_w1 = (const float*)d_in[2];
    const float* fx_b1 = (const float*)d_in[3];
    const float* fx_w2 = (const float*)d_in[4];
    const float* fx_b2 = (const float*)d_in[5];
    const float* fx_w3 = (const float*)d_in[6];
    const float* fx_b3 = (const float*)d_in[7];
    const float* fg_w1 = (const float*)d_in[8];
    const float* fg_b1 = (const float*)d_in[9];
    const float* fg_w2 = (const float*)d_in[10];
    const float* fg_b2 = (const float*)d_in[11];
    const float* fg_w3 = (const float*)d_in[12];
    const float* fg_b3 = (const float*)d_in[13];
    const float* c1_w  = (const float*)d_in[14];
    const float* c1_b  = (const float*)d_in[15];
    const float* c2_w  = (const float*)d_in[16];
    const float* c2_b  = (const float*)d_in[17];
    const float* c3_w  = (const float*)d_in[18];
    const float* c3_b  = (const float*)d_in[19];
    float* out = (float*)d_out;

    __half *h1x, *h1g, *h2x, *h2g;
    float *xy; uint32_t *wq8, *wq11;
    cudaGetSymbolAddress((void**)&h1x, g_h1x);
    cudaGetSymbolAddress((void**)&h1g, g_h1g);
    cudaGetSymbolAddress((void**)&h2x, g_h2x);
    cudaGetSymbolAddress((void**)&h2g, g_h2g);
    cudaGetSymbolAddress((void**)&xy, g_xy);
    cudaGetSymbolAddress((void**)&wq8, g_wq8);
    cudaGetSymbolAddress((void**)&wq11, g_wq11);

    const size_t W8 = 9*4*8*32*2;
    const size_t W11 = 9*4*11*32*2;
    uint32_t* wq_fx2 = wq8;
    uint32_t* wq_fg2 = wq8 + W8;
    uint32_t* wq_c2  = wq8 + 2*W8;
    uint32_t* wq_fx3 = wq11;
    uint32_t* wq_fg3 = wq11 + W11;

    const int PIX_BLOCKS = Nn*HW/256;      // 4096
    const int C64_BLOCKS = Nn*128*4;       // 8192
    const int OUT_BLOCKS = Nn*256*4;       // 16384

    const int AH = 4*66*144;               // 38016
    const int SM64 = AH + 64*4;
    const int SM88 = AH + 88*4;
    const int SMO  = 3*66*144 + 576*4;

    cudaFuncSetAttribute((const void*)conv64m<8, 64, false, true>,
                         cudaFuncAttributeMaxDynamicSharedMemorySize, SM64);
    cudaFuncSetAttribute((const void*)conv64m<8, 64, false, false>,
                         cudaFuncAttributeMaxDynamicSharedMemorySize, SM64);
    cudaFuncSetAttribute((const void*)conv64m<11, 81, true, true>,
                         cudaFuncAttributeMaxDynamicSharedMemorySize, SM88);
    cudaFuncSetAttribute((const void*)conv_out1,
                         cudaFuncAttributeMaxDynamicSharedMemorySize, SMO);

    const int PQ64 = (9*4*8*32 + 255)/256;   // 36
    const int PQ88 = (9*4*11*32 + 255)/256;  // 50

    // ---- all weight prepacks up front (depend only on inputs) ----
    prepack_wq<8, 64><<<PQ64, 256>>>(fx_w2, wq_fx2);
    prepack_wq<8, 64><<<PQ64, 256>>>(fg_w2, wq_fg2);
    prepack_wq<8, 64><<<PQ64, 256>>>(c2_w,  wq_c2);
    prepack_wq<11, 81><<<PQ88, 256>>>(fx_w3, wq_fx3);
    prepack_wq<11, 81><<<PQ88, 256>>>(fg_w3, wq_fg3);

    // ---- batched x+g heads ----
    conv_in_small<1, true><<<2*PIX_BLOCKS, 256>>>(
        x, fx_w1, fx_b1, h1x, g, fg_w1, fg_b1, h1g);
    conv64m<8, 64, false, true><<<2*C64_BLOCKS, 128, SM64>>>(
        h1x, wq_fx2, fx_b2, h2x, nullptr,
        h1g, wq_fg2, fg_b2, h2g, nullptr, nullptr);
    conv64m<11, 81, true, true><<<2*C64_BLOCKS, 128, SM88>>>(
        h2x, wq_fx3, fx_b3, nullptr, x,
        h2g, wq_fg3, fg_b3, nullptr, g, xy);

    // ---- fusion head ----
    conv_in_small<2, false><<<PIX_BLOCKS, 256>>>(
        xy, c1_w, c1_b, h1x, nullptr, nullptr, nullptr, nullptr);
    conv64m<8, 64, false, false><<<C64_BLOCKS, 128, SM64>>>(
        h1x, wq_c2, c2_b, h2x, nullptr,
        nullptr, nullptr, nullptr, nullptr, nullptr, nullptr);
    conv_out1<<<OUT_BLOCKS, 64, SMO>>>(h2x, c3_w, c3_b, out);
}

// round 12
// speedup vs baseline: 2.8947x; 1.0506x over previous
#include <cuda_runtime.h>
#include <cuda_fp16.h>
#include <cstdint>
#include <math.h>

#define Nn 16
#define Hh 256
#define Ww 256
#define HW (Hh*Ww)

// ---------------- scratch (device globals; no allocation allowed) ----------------
__device__ __half g_h1x[(size_t)Nn*HW*64];
__device__ __half g_h1g[(size_t)Nn*HW*64];
__device__ __half g_h2x[(size_t)Nn*HW*64];
__device__ __half g_h2g[(size_t)Nn*HW*64];
__device__ float g_xy[(size_t)Nn*2*HW];
__device__ __align__(16) uint32_t g_wq8[3][9*8*2*32*4];    // fx2, fg2, c2
__device__ __align__(16) uint32_t g_wq11[2][9*11*2*32*4];  // fx3, fg3
__device__ __align__(16) uint32_t g_wq1[9*1*2*32*4];       // c3

__device__ __forceinline__ void mma_f16(float* c, const uint32_t* a, uint32_t b0, uint32_t b1) {
    asm volatile("mma.sync.aligned.m16n8k16.row.col.f32.f16.f16.f32 "
        "{%0,%1,%2,%3},{%4,%5,%6,%7},{%8,%9},{%0,%1,%2,%3};"
        : "+f"(c[0]), "+f"(c[1]), "+f"(c[2]), "+f"(c[3])
        : "r"(a[0]), "r"(a[1]), "r"(a[2]), "r"(a[3]), "r"(b0), "r"(b1));
}
__device__ __forceinline__ void ldm_x4(uint32_t* r, uint32_t saddr) {
    asm volatile("ldmatrix.sync.aligned.m8n8.x4.shared.b16 {%0,%1,%2,%3}, [%4];"
        : "=r"(r[0]), "=r"(r[1]), "=r"(r[2]), "=r"(r[3]) : "r"(saddr));
}
__device__ __forceinline__ uint32_t pkh2(float a, float b) {
    return (uint32_t)__half_as_ushort(__float2half_rn(a)) |
           ((uint32_t)__half_as_ushort(__float2half_rn(b)) << 16);
}

// ------------- weight prepack: w[co][ci][3][3] fp32 -> uint4 B fragments ----------------
// layout: [tap][nt][k2][lane] x uint4 { k=2*k2 reg0, k reg1, k+1 reg0, k+1 reg1 }
template<int NT, int CO>
__global__ void prepack_wq(const float* __restrict__ w, uint32_t* __restrict__ o) {
    int idx = blockIdx.x * 256 + threadIdx.x;
    if (idx >= 9*NT*2*32) return;
    int lane = idx & 31;
    int k2 = (idx >> 5) & 1;
    int nt = (idx >> 6) % NT;
    int tap = idx / (64*NT);
    int lg = lane >> 2, lt = lane & 3;
    int co = nt*8 + lg;
    auto wv = [&](int ci) -> uint32_t {
        float v = (co < CO) ? w[((size_t)co*64 + ci)*9 + tap] : 0.f;
        return (uint32_t)__half_as_ushort(__float2half_rn(v));
    };
    uint32_t r[4];
    #pragma unroll
    for (int kk = 0; kk < 2; kk++) {
        int c0 = (k2*2 + kk)*16 + lt*2;
        r[kk*2+0] = wv(c0)   | (wv(c0+1) << 16);
        r[kk*2+1] = wv(c0+8) | (wv(c0+9) << 16);
    }
    ((uint4*)o)[idx] = make_uint4(r[0], r[1], r[2], r[3]);
}

// ---------------- conv 3x3, small Cin -> 64 relu, writes fp16 NHWC. Optional 2 heads. ----
// PIX_BLOCKS per head = 4096 = 2^12.
template<int CIN, bool DUAL>
__global__ __launch_bounds__(256) void conv_in_small(
    const float* __restrict__ in0, const float* __restrict__ w0, const float* __restrict__ b0,
    __half* __restrict__ oh0,
    const float* __restrict__ in1, const float* __restrict__ w1, const float* __restrict__ b1,
    __half* __restrict__ oh1)
{
    __shared__ float s_w[64*CIN*9];
    __shared__ float s_b[64];
    int tid = threadIdx.x;
    int head = DUAL ? (int)(blockIdx.x >> 12) : 0;
    const float* in = head ? in1 : in0;
    const float* w  = head ? w1 : w0;
    const float* b  = head ? b1 : b0;
    __half* oh      = head ? oh1 : oh0;

    for (int i = tid; i < 64*CIN*9; i += 256) s_w[i] = w[i];
    if (tid < 64) s_b[tid] = b[tid];
    __syncthreads();

    int px = (DUAL ? (int)(blockIdx.x & 4095) : (int)blockIdx.x)*256 + tid;
    int n = px >> 16; int rem = px & 65535;
    int y = rem >> 8;  int x = rem & 255;

    float iv[CIN*9];
    #pragma unroll
    for (int c = 0; c < CIN; c++)
        #pragma unroll
        for (int kh = 0; kh < 3; kh++)
            #pragma unroll
            for (int kw = 0; kw < 3; kw++) {
                int yy = y + kh - 1, xx = x + kw - 1;
                float v = 0.f;
                if (yy >= 0 && yy < Hh && xx >= 0 && xx < Ww)
                    v = in[((size_t)n*CIN + c)*HW + yy*Ww + xx];
                iv[c*9 + kh*3 + kw] = v;
            }

    float a[64];
    #pragma unroll
    for (int co = 0; co < 64; co++) {
        float s = s_b[co];
        #pragma unroll
        for (int i = 0; i < CIN*9; i++) s += s_w[co*CIN*9 + i] * iv[i];
        a[co] = fmaxf(s, 0.f);
    }

    char* ph = (char*)oh + (size_t)px * 128;
    #pragma unroll
    for (int q = 0; q < 8; q++) {
        uint32_t hw[4];
        #pragma unroll
        for (int t = 0; t < 4; t++)
            hw[t] = pkh2(a[q*8 + t*2], a[q*8 + t*2 + 1]);
        *(uint4*)(ph + q*16) = make_uint4(hw[0], hw[1], hw[2], hw[3]);
    }
}

// ---------------- mma.sync conv 3x3, 64 -> CO, fp16, single pass. -------------------
// MODE: 0 = bias+relu -> fp16 NHWC; 1 = fused softmax+9x9 filter -> xy;
//       2 = bias -> fp32 planar (channel 0 only; CO=1 padded to 8)
// C64_BLOCKS per head = 8192 = 2^13.
template<int NT, int CO, int MODE, bool DUAL>
__global__ __launch_bounds__(128, (NT == 1) ? 5 : ((NT == 8) ? 4 : 3)) void conv64m(
    const __half* __restrict__ ih0, const uint32_t* __restrict__ wq0,
    const float* __restrict__ bias0, __half* __restrict__ oh0, const float* __restrict__ fsrc0,
    const __half* __restrict__ ih1, const uint32_t* __restrict__ wq1,
    const float* __restrict__ bias1, __half* __restrict__ oh1, const float* __restrict__ fsrc1,
    float* __restrict__ xy)
{
    constexpr int CP = NT * 8;
    constexpr int AH = 4*66*144;          // 38016 bytes
    extern __shared__ char sm[];
    char* sA = sm;
    float* s_bias = (float*)(sm + AH);

    int tid = threadIdx.x;
    int lane = tid & 31, wid = tid >> 5;
    int lg = lane >> 2, lt = lane & 3;
    int py = wid >> 1, xb = (wid & 1) * 32;

    int bid = blockIdx.x;
    int head = DUAL ? (bid >> 13) : 0;
    bid &= 8191;                          // 16n x 128yp x 4xq
    const __half* ih = head ? ih1 : ih0;
    const uint32_t* wq = head ? wq1 : wq0;
    const float* bias = head ? bias1 : bias0;
    __half* oh = head ? oh1 : oh0;
    const float* fsrc = head ? fsrc1 : fsrc0;

    int xq = bid & 3;
    int yp = (bid >> 2) & 127;
    int n  = bid >> 9;
    int y0 = yp * 2, x0 = xq * 64;
    size_t nbase = (size_t)n * 65536;

    if (tid < CP) s_bias[tid] = (tid < CO) ? bias[tid] : 0.f;

    // stage A tile from fp16 global (zero halo = conv zero-padding)
    for (int idx = tid; idx < 4*66*8; idx += 128) {
        int c = idx & 7, e = idx >> 3;
        int row = e / 66, px = e - row*66;
        int gy = y0 + row - 1, gx = x0 + px - 1;
        uint4 vh = make_uint4(0,0,0,0);
        if ((unsigned)gy < 256u && (unsigned)gx < 256u)
            vh = *(const uint4*)((const char*)ih + (nbase + gy*256 + gx)*128 + c*16);
        *(uint4*)(sA + (row*66 + px)*144 + c*16) = vh;
    }
    __syncthreads();

    float acc[2][NT][4];
    #pragma unroll
    for (int mt = 0; mt < 2; mt++)
        #pragma unroll
        for (int nt = 0; nt < NT; nt++)
            #pragma unroll
            for (int j = 0; j < 4; j++) acc[mt][nt][j] = 0.f;

    uint32_t sA_s = (uint32_t)__cvta_generic_to_shared(sA);
    uint32_t rbase = (uint32_t)((lane & 15) * 144 + ((lane >> 4) << 4));
    const uint4* wq4 = (const uint4*)wq;

    #pragma unroll 1
    for (int tap = 0; tap < 9; tap++) {
        int kh = tap / 3, kw = tap - kh*3;
        uint32_t base0 = sA_s + (uint32_t)(((py + kh)*66 + xb + kw)*144) + rbase;
        const uint4* wt = wq4 + (size_t)tap*NT*2*32 + lane;
        #pragma unroll
        for (int k2 = 0; k2 < 2; k2++) {
            uint32_t ah[2][2][4];   // [kk][mt][4]
            #pragma unroll
            for (int kk = 0; kk < 2; kk++)
                #pragma unroll
                for (int mt = 0; mt < 2; mt++)
                    ldm_x4(ah[kk][mt], base0 + mt*2304 + (k2*2 + kk)*32);
            #pragma unroll
            for (int nt = 0; nt < NT; nt++) {
                uint4 bb = wt[(nt*2 + k2)*32];
                #pragma unroll
                for (int mt = 0; mt < 2; mt++) {
                    mma_f16(acc[mt][nt], ah[0][mt], bb.x, bb.y);
                    mma_f16(acc[mt][nt], ah[1][mt], bb.z, bb.w);
                }
            }
        }
    }

    if constexpr (MODE == 0) {
        // bias + relu + fp16 global
        #pragma unroll
        for (int mt = 0; mt < 2; mt++) {
            size_t pix0 = nbase + (size_t)(y0 + py)*256 + x0 + xb + mt*16 + lg;
            #pragma unroll
            for (int nt = 0; nt < NT; nt++) {
                int co = nt*8 + lt*2;
                float b0 = s_bias[co], b1v = s_bias[co+1];
                *(uint32_t*)((char*)oh + pix0*128 + co*2) =
                    pkh2(fmaxf(acc[mt][nt][0] + b0, 0.f), fmaxf(acc[mt][nt][1] + b1v, 0.f));
                *(uint32_t*)((char*)oh + (pix0+8)*128 + co*2) =
                    pkh2(fmaxf(acc[mt][nt][2] + b0, 0.f), fmaxf(acc[mt][nt][3] + b1v, 0.f));
            }
        }
    } else if constexpr (MODE == 1) {
        // fused softmax over 81 logits + 9x9 pixel-adaptive filtering
        const float* sp = fsrc + nbase;
        int Y = y0 + py;
        #pragma unroll
        for (int mt = 0; mt < 2; mt++) {
            #pragma unroll
            for (int r = 0; r < 2; r++) {
                int X = x0 + xb + mt*16 + lg + r*8;
                float v[NT][2];
                float mx = -1e30f;
                #pragma unroll
                for (int nt = 0; nt < NT; nt++) {
                    #pragma unroll
                    for (int j = 0; j < 2; j++) {
                        int co = nt*8 + lt*2 + j;
                        v[nt][j] = acc[mt][nt][r*2 + j] + s_bias[co];
                        if (co < 81) mx = fmaxf(mx, v[nt][j]);
                    }
                }
                mx = fmaxf(mx, __shfl_xor_sync(0xffffffffu, mx, 1));
                mx = fmaxf(mx, __shfl_xor_sync(0xffffffffu, mx, 2));
                float se = 0.f, fo = 0.f;
                #pragma unroll
                for (int nt = 0; nt < NT; nt++) {
                    #pragma unroll
                    for (int j = 0; j < 2; j++) {
                        int co = nt*8 + lt*2 + j;
                        if (co < 81) {
                            float e = __expf(v[nt][j] - mx);
                            se += e;
                            int kh = co / 9, kw = co - kh*9;
                            int sy = Y + kh - 4, sx2 = X + kw - 4;
                            float sv = 0.f;
                            if ((unsigned)sy < 256u && (unsigned)sx2 < 256u)
                                sv = sp[sy*256 + sx2];
                            fo += e * sv;
                        }
                    }
                }
                se += __shfl_xor_sync(0xffffffffu, se, 1);
                se += __shfl_xor_sync(0xffffffffu, se, 2);
                fo += __shfl_xor_sync(0xffffffffu, fo, 1);
                fo += __shfl_xor_sync(0xffffffffu, fo, 2);
                if (lt == 0)
                    xy[((size_t)n*2 + head)*HW + Y*256 + X] = fo / se;
            }
        }
    } else {
        // MODE 2: fp32 planar out, channel 0 only (lt==0, j==0 lanes hold co=0)
        float b0 = s_bias[0];
        if (lt == 0) {
            #pragma unroll
            for (int mt = 0; mt < 2; mt++)
                #pragma unroll
                for (int r = 0; r < 2; r++) {
                    int X = x0 + xb + mt*16 + lg + r*8;
                    xy[nbase + (size_t)(y0 + py)*256 + X] = acc[mt][0][r*2] + b0;
                }
        }
    }
}

// ---------------- launch ----------------
extern "C" void kernel_launch(void* const* d_in, const int* in_sizes, int n_in,
                              void* d_out, int out_size)
{
    const float* x     = (const float*)d_in[0];
    const float* g     = (const float*)d_in[1];
    const float* fx_w1 = (const float*)d_in[2];
    const float* fx_b1 = (const float*)d_in[3];
    const float* fx_w2 = (const float*)d_in[4];
    const float* fx_b2 = (const float*)d_in[5];
    const float* fx_w3 = (const float*)d_in[6];
    const float* fx_b3 = (const float*)d_in[7];
    const float* fg_w1 = (const float*)d_in[8];
    const float* fg_b1 = (const float*)d_in[9];
    const float* fg_w2 = (const float*)d_in[10];
    const float* fg_b2 = (const float*)d_in[11];
    const float* fg_w3 = (const float*)d_in[12];
    const float* fg_b3 = (const float*)d_in[13];
    const float* c1_w  = (const float*)d_in[14];
    const float* c1_b  = (const float*)d_in[15];
    const float* c2_w  = (const float*)d_in[16];
    const float* c2_b  = (const float*)d_in[17];
    const float* c3_w  = (const float*)d_in[18];
    const float* c3_b  = (const float*)d_in[19];
    float* out = (float*)d_out;

    __half *h1x, *h1g, *h2x, *h2g;
    float *xy; uint32_t *wq8, *wq11, *wq1;
    cudaGetSymbolAddress((void**)&h1x, g_h1x);
    cudaGetSymbolAddress((void**)&h1g, g_h1g);
    cudaGetSymbolAddress((void**)&h2x, g_h2x);
    cudaGetSymbolAddress((void**)&h2g, g_h2g);
    cudaGetSymbolAddress((void**)&xy, g_xy);
    cudaGetSymbolAddress((void**)&wq8, g_wq8);
    cudaGetSymbolAddress((void**)&wq11, g_wq11);
    cudaGetSymbolAddress((void**)&wq1, g_wq1);

    const size_t W8 = 9*8*2*32*4;
    const size_t W11 = 9*11*2*32*4;
    uint32_t* wq_fx2 = wq8;
    uint32_t* wq_fg2 = wq8 + W8;
    uint32_t* wq_c2  = wq8 + 2*W8;
    uint32_t* wq_fx3 = wq11;
    uint32_t* wq_fg3 = wq11 + W11;

    const int PIX_BLOCKS = Nn*HW/256;      // 4096
    const int C64_BLOCKS = Nn*128*4;       // 8192

    const int AH = 4*66*144;               // 38016
    const int SM64 = AH + 64*4;
    const int SM88 = AH + 88*4;
    const int SM8  = AH + 8*4;

    cudaFuncSetAttribute((const void*)conv64m<8, 64, 0, true>,
                         cudaFuncAttributeMaxDynamicSharedMemorySize, SM64);
    cudaFuncSetAttribute((const void*)conv64m<8, 64, 0, false>,
                         cudaFuncAttributeMaxDynamicSharedMemorySize, SM64);
    cudaFuncSetAttribute((const void*)conv64m<11, 81, 1, true>,
                         cudaFuncAttributeMaxDynamicSharedMemorySize, SM88);
    cudaFuncSetAttribute((const void*)conv64m<1, 1, 2, false>,
                         cudaFuncAttributeMaxDynamicSharedMemorySize, SM8);

    const int PQ8  = (9*8*2*32 + 255)/256;   // 18
    const int PQ11 = (9*11*2*32 + 255)/256;  // 25
    const int PQ1  = (9*1*2*32 + 255)/256;   // 3

    // ---- all weight prepacks up front (depend only on inputs) ----
    prepack_wq<8, 64><<<PQ8, 256>>>(fx_w2, wq_fx2);
    prepack_wq<8, 64><<<PQ8, 256>>>(fg_w2, wq_fg2);
    prepack_wq<8, 64><<<PQ8, 256>>>(c2_w,  wq_c2);
    prepack_wq<11, 81><<<PQ11, 256>>>(fx_w3, wq_fx3);
    prepack_wq<11, 81><<<PQ11, 256>>>(fg_w3, wq_fg3);
    prepack_wq<1, 1><<<PQ1, 256>>>(c3_w, wq1);

    // ---- batched x+g heads ----
    conv_in_small<1, true><<<2*PIX_BLOCKS, 256>>>(
        x, fx_w1, fx_b1, h1x, g, fg_w1, fg_b1, h1g);
    conv64m<8, 64, 0, true><<<2*C64_BLOCKS, 128, SM64>>>(
        h1x, wq_fx2, fx_b2, h2x, nullptr,
        h1g, wq_fg2, fg_b2, h2g, nullptr, nullptr);
    conv64m<11, 81, 1, true><<<2*C64_BLOCKS, 128, SM88>>>(
        h2x, wq_fx3, fx_b3, nullptr, x,
        h2g, wq_fg3, fg_b3, nullptr, g, xy);

    // ---- fusion head ----
    conv_in_small<2, false><<<PIX_BLOCKS, 256>>>(
        xy, c1_w, c1_b, h1x, nullptr, nullptr, nullptr, nullptr);
    conv64m<8, 64, 0, false><<<C64_BLOCKS, 128, SM64>>>(
        h1x, wq_c2, c2_b, h2x, nullptr,
        nullptr, nullptr, nullptr, nullptr, nullptr, nullptr);
    conv64m<1, 1, 2, false><<<C64_BLOCKS, 128, SM8>>>(
        h2x, wq1, c3_b, nullptr, nullptr,
        nullptr, nullptr, nullptr, nullptr, nullptr, out);
}

// round 13
// speedup vs baseline: 3.0714x; 1.0610x over previous
#include <cuda_runtime.h>
#include <cuda_fp16.h>
#include <cstdint>
#include <math.h>

#define Nn 16
#define Hh 256
#define Ww 256
#define HW (Hh*Ww)

// ---------------- scratch (device globals; no allocation allowed) ----------------
__device__ __half g_h1x[(size_t)Nn*HW*64];
__device__ __half g_h1g[(size_t)Nn*HW*64];
__device__ __half g_h2x[(size_t)Nn*HW*64];
__device__ __half g_h2g[(size_t)Nn*HW*64];
__device__ float g_xy[(size_t)Nn*2*HW];
__device__ __align__(16) uint32_t g_wq8[3][9*8*2*32*4];    // fx2, fg2, c2
__device__ __align__(16) uint32_t g_wq11[2][9*11*2*32*4];  // fx3, fg3
__device__ __align__(16) uint32_t g_wq1[9*1*2*32*4];       // c3

__device__ __forceinline__ void mma_f16(float* c, const uint32_t* a, uint32_t b0, uint32_t b1) {
    asm volatile("mma.sync.aligned.m16n8k16.row.col.f32.f16.f16.f32 "
        "{%0,%1,%2,%3},{%4,%5,%6,%7},{%8,%9},{%0,%1,%2,%3};"
        : "+f"(c[0]), "+f"(c[1]), "+f"(c[2]), "+f"(c[3])
        : "r"(a[0]), "r"(a[1]), "r"(a[2]), "r"(a[3]), "r"(b0), "r"(b1));
}
__device__ __forceinline__ void ldm_x4(uint32_t* r, uint32_t saddr) {
    asm volatile("ldmatrix.sync.aligned.m8n8.x4.shared.b16 {%0,%1,%2,%3}, [%4];"
        : "=r"(r[0]), "=r"(r[1]), "=r"(r[2]), "=r"(r[3]) : "r"(saddr));
}
__device__ __forceinline__ uint32_t pkh2(float a, float b) {
    return (uint32_t)__half_as_ushort(__float2half_rn(a)) |
           ((uint32_t)__half_as_ushort(__float2half_rn(b)) << 16);
}

// ------------- weight prepack: w[co][ci][3][3] fp32 -> uint4 B fragments ----------------
// layout: [tap][nt][k2][lane] x uint4 { k=2*k2 reg0, k reg1, k+1 reg0, k+1 reg1 }
template<int NT, int CO>
__global__ void prepack_wq(const float* __restrict__ w, uint32_t* __restrict__ o) {
    int idx = blockIdx.x * 256 + threadIdx.x;
    if (idx >= 9*NT*2*32) return;
    int lane = idx & 31;
    int k2 = (idx >> 5) & 1;
    int nt = (idx >> 6) % NT;
    int tap = idx / (64*NT);
    int lg = lane >> 2, lt = lane & 3;
    int co = nt*8 + lg;
    auto wv = [&](int ci) -> uint32_t {
        float v = (co < CO) ? w[((size_t)co*64 + ci)*9 + tap] : 0.f;
        return (uint32_t)__half_as_ushort(__float2half_rn(v));
    };
    uint32_t r[4];
    #pragma unroll
    for (int kk = 0; kk < 2; kk++) {
        int c0 = (k2*2 + kk)*16 + lt*2;
        r[kk*2+0] = wv(c0)   | (wv(c0+1) << 16);
        r[kk*2+1] = wv(c0+8) | (wv(c0+9) << 16);
    }
    ((uint4*)o)[idx] = make_uint4(r[0], r[1], r[2], r[3]);
}

// ---------------- conv 3x3, small Cin -> 64 relu, writes fp16 NHWC. Optional 2 heads. ----
// PIX_BLOCKS per head = 4096 = 2^12.
template<int CIN, bool DUAL>
__global__ __launch_bounds__(256) void conv_in_small(
    const float* __restrict__ in0, const float* __restrict__ w0, const float* __restrict__ b0,
    __half* __restrict__ oh0,
    const float* __restrict__ in1, const float* __restrict__ w1, const float* __restrict__ b1,
    __half* __restrict__ oh1)
{
    __shared__ float s_w[64*CIN*9];
    __shared__ float s_b[64];
    int tid = threadIdx.x;
    int head = DUAL ? (int)(blockIdx.x >> 12) : 0;
    const float* in = head ? in1 : in0;
    const float* w  = head ? w1 : w0;
    const float* b  = head ? b1 : b0;
    __half* oh      = head ? oh1 : oh0;

    for (int i = tid; i < 64*CIN*9; i += 256) s_w[i] = w[i];
    if (tid < 64) s_b[tid] = b[tid];
    __syncthreads();

    int px = (DUAL ? (int)(blockIdx.x & 4095) : (int)blockIdx.x)*256 + tid;
    int n = px >> 16; int rem = px & 65535;
    int y = rem >> 8;  int x = rem & 255;

    float iv[CIN*9];
    #pragma unroll
    for (int c = 0; c < CIN; c++)
        #pragma unroll
        for (int kh = 0; kh < 3; kh++)
            #pragma unroll
            for (int kw = 0; kw < 3; kw++) {
                int yy = y + kh - 1, xx = x + kw - 1;
                float v = 0.f;
                if (yy >= 0 && yy < Hh && xx >= 0 && xx < Ww)
                    v = in[((size_t)n*CIN + c)*HW + yy*Ww + xx];
                iv[c*9 + kh*3 + kw] = v;
            }

    float a[64];
    #pragma unroll
    for (int co = 0; co < 64; co++) {
        float s = s_b[co];
        #pragma unroll
        for (int i = 0; i < CIN*9; i++) s += s_w[co*CIN*9 + i] * iv[i];
        a[co] = fmaxf(s, 0.f);
    }

    char* ph = (char*)oh + (size_t)px * 128;
    #pragma unroll
    for (int q = 0; q < 8; q++) {
        uint32_t hw[4];
        #pragma unroll
        for (int t = 0; t < 4; t++)
            hw[t] = pkh2(a[q*8 + t*2], a[q*8 + t*2 + 1]);
        *(uint4*)(ph + q*16) = make_uint4(hw[0], hw[1], hw[2], hw[3]);
    }
}

// ---------------- mma.sync conv 3x3, 64 -> CO, fp16, single pass. -------------------
// CTA tile: 4 y-rows x 32 x (M=128). A tile: 6 rows x 34 px x 144B = 29376 B.
// Warp: one y-row x 32 px (2 m16 tiles).
// MODE: 0 = bias+relu -> fp16 NHWC; 1 = fused softmax+9x9 filter -> xy;
//       2 = bias -> fp32 planar (channel 0 only; CO=1 padded to 8)
// Blocks per head = 16n x 64yq x 8xq = 8192 = 2^13.
template<int NT, int CO, int MODE, bool DUAL>
__global__ __launch_bounds__(128, (NT == 1) ? 5 : ((NT == 8) ? 4 : 3)) void conv64m(
    const __half* __restrict__ ih0, const uint32_t* __restrict__ wq0,
    const float* __restrict__ bias0, __half* __restrict__ oh0, const float* __restrict__ fsrc0,
    const __half* __restrict__ ih1, const uint32_t* __restrict__ wq1,
    const float* __restrict__ bias1, __half* __restrict__ oh1, const float* __restrict__ fsrc1,
    float* __restrict__ xy)
{
    constexpr int CP = NT * 8;
    constexpr int AH = 6*34*144;          // 29376 bytes
    extern __shared__ char sm[];
    char* sA = sm;
    float* s_bias = (float*)(sm + AH);

    int tid = threadIdx.x;
    int lane = tid & 31, wid = tid >> 5;
    int lg = lane >> 2, lt = lane & 3;
    int py = wid;                         // warp = one y-row

    int bid = blockIdx.x;
    int head = DUAL ? (bid >> 13) : 0;
    bid &= 8191;                          // 16n x 64yq x 8xq
    const __half* ih = head ? ih1 : ih0;
    const uint32_t* wq = head ? wq1 : wq0;
    const float* bias = head ? bias1 : bias0;
    __half* oh = head ? oh1 : oh0;
    const float* fsrc = head ? fsrc1 : fsrc0;

    int xq = bid & 7;
    int yq = (bid >> 3) & 63;
    int n  = bid >> 9;
    int y0 = yq * 4, x0 = xq * 32;
    size_t nbase = (size_t)n * 65536;

    if (tid < CP) s_bias[tid] = (tid < CO) ? bias[tid] : 0.f;

    // stage A tile from fp16 global (zero halo = conv zero-padding)
    for (int idx = tid; idx < 6*34*8; idx += 128) {
        int c = idx & 7, e = idx >> 3;
        int row = e / 34, px = e - row*34;
        int gy = y0 + row - 1, gx = x0 + px - 1;
        uint4 vh = make_uint4(0,0,0,0);
        if ((unsigned)gy < 256u && (unsigned)gx < 256u)
            vh = *(const uint4*)((const char*)ih + (nbase + gy*256 + gx)*128 + c*16);
        *(uint4*)(sA + (row*34 + px)*144 + c*16) = vh;
    }
    __syncthreads();

    float acc[2][NT][4];
    #pragma unroll
    for (int mt = 0; mt < 2; mt++)
        #pragma unroll
        for (int nt = 0; nt < NT; nt++)
            #pragma unroll
            for (int j = 0; j < 4; j++) acc[mt][nt][j] = 0.f;

    uint32_t sA_s = (uint32_t)__cvta_generic_to_shared(sA);
    uint32_t rbase = (uint32_t)((lane & 15) * 144 + ((lane >> 4) << 4));
    const uint4* wq4 = (const uint4*)wq;

    #pragma unroll 1
    for (int tap = 0; tap < 9; tap++) {
        int kh = tap / 3, kw = tap - kh*3;
        uint32_t base0 = sA_s + (uint32_t)(((py + kh)*34 + kw)*144) + rbase;
        const uint4* wt = wq4 + (size_t)tap*NT*2*32 + lane;
        #pragma unroll
        for (int k2 = 0; k2 < 2; k2++) {
            uint32_t ah[2][2][4];   // [kk][mt][4]
            #pragma unroll
            for (int kk = 0; kk < 2; kk++)
                #pragma unroll
                for (int mt = 0; mt < 2; mt++)
                    ldm_x4(ah[kk][mt], base0 + mt*2304 + (k2*2 + kk)*32);
            #pragma unroll
            for (int nt = 0; nt < NT; nt++) {
                uint4 bb = wt[(nt*2 + k2)*32];
                #pragma unroll
                for (int mt = 0; mt < 2; mt++) {
                    mma_f16(acc[mt][nt], ah[0][mt], bb.x, bb.y);
                    mma_f16(acc[mt][nt], ah[1][mt], bb.z, bb.w);
                }
            }
        }
    }

    int Y = y0 + py;
    if constexpr (MODE == 0) {
        // bias + relu + fp16 global
        #pragma unroll
        for (int mt = 0; mt < 2; mt++) {
            size_t pix0 = nbase + (size_t)Y*256 + x0 + mt*16 + lg;
            #pragma unroll
            for (int nt = 0; nt < NT; nt++) {
                int co = nt*8 + lt*2;
                float b0 = s_bias[co], b1v = s_bias[co+1];
                *(uint32_t*)((char*)oh + pix0*128 + co*2) =
                    pkh2(fmaxf(acc[mt][nt][0] + b0, 0.f), fmaxf(acc[mt][nt][1] + b1v, 0.f));
                *(uint32_t*)((char*)oh + (pix0+8)*128 + co*2) =
                    pkh2(fmaxf(acc[mt][nt][2] + b0, 0.f), fmaxf(acc[mt][nt][3] + b1v, 0.f));
            }
        }
    } else if constexpr (MODE == 1) {
        // fused softmax over 81 logits + 9x9 pixel-adaptive filtering
        const float* sp = fsrc + nbase;
        #pragma unroll
        for (int mt = 0; mt < 2; mt++) {
            #pragma unroll
            for (int r = 0; r < 2; r++) {
                int X = x0 + mt*16 + lg + r*8;
                float v[NT][2];
                float mx = -1e30f;
                #pragma unroll
                for (int nt = 0; nt < NT; nt++) {
                    #pragma unroll
                    for (int j = 0; j < 2; j++) {
                        int co = nt*8 + lt*2 + j;
                        v[nt][j] = acc[mt][nt][r*2 + j] + s_bias[co];
                        if (co < 81) mx = fmaxf(mx, v[nt][j]);
                    }
                }
                mx = fmaxf(mx, __shfl_xor_sync(0xffffffffu, mx, 1));
                mx = fmaxf(mx, __shfl_xor_sync(0xffffffffu, mx, 2));
                float se = 0.f, fo = 0.f;
                #pragma unroll
                for (int nt = 0; nt < NT; nt++) {
                    #pragma unroll
                    for (int j = 0; j < 2; j++) {
                        int co = nt*8 + lt*2 + j;
                        if (co < 81) {
                            float e = __expf(v[nt][j] - mx);
                            se += e;
                            int kh = co / 9, kw = co - kh*9;
                            int sy = Y + kh - 4, sx2 = X + kw - 4;
                            float sv = 0.f;
                            if ((unsigned)sy < 256u && (unsigned)sx2 < 256u)
                                sv = sp[sy*256 + sx2];
                            fo += e * sv;
                        }
                    }
                }
                se += __shfl_xor_sync(0xffffffffu, se, 1);
                se += __shfl_xor_sync(0xffffffffu, se, 2);
                fo += __shfl_xor_sync(0xffffffffu, fo, 1);
                fo += __shfl_xor_sync(0xffffffffu, fo, 2);
                if (lt == 0)
                    xy[((size_t)n*2 + head)*HW + Y*256 + X] = fo / se;
            }
        }
    } else {
        // MODE 2: fp32 planar out, channel 0 only (lt==0, j==0 lanes hold co=0)
        float b0 = s_bias[0];
        if (lt == 0) {
            #pragma unroll
            for (int mt = 0; mt < 2; mt++)
                #pragma unroll
                for (int r = 0; r < 2; r++) {
                    int X = x0 + mt*16 + lg + r*8;
                    xy[nbase + (size_t)Y*256 + X] = acc[mt][0][r*2] + b0;
                }
        }
    }
}

// ---------------- launch ----------------
extern "C" void kernel_launch(void* const* d_in, const int* in_sizes, int n_in,
                              void* d_out, int out_size)
{
    const float* x     = (const float*)d_in[0];
    const float* g     = (const float*)d_in[1];
    const float* fx_w1 = (const float*)d_in[2];
    const float* fx_b1 = (const float*)d_in[3];
    const float* fx_w2 = (const float*)d_in[4];
    const float* fx_b2 = (const float*)d_in[5];
    const float* fx_w3 = (const float*)d_in[6];
    const float* fx_b3 = (const float*)d_in[7];
    const float* fg_w1 = (const float*)d_in[8];
    const float* fg_b1 = (const float*)d_in[9];
    const float* fg_w2 = (const float*)d_in[10];
    const float* fg_b2 = (const float*)d_in[11];
    const float* fg_w3 = (const float*)d_in[12];
    const float* fg_b3 = (const float*)d_in[13];
    const float* c1_w  = (const float*)d_in[14];
    const float* c1_b  = (const float*)d_in[15];
    const float* c2_w  = (const float*)d_in[16];
    const float* c2_b  = (const float*)d_in[17];
    const float* c3_w  = (const float*)d_in[18];
    const float* c3_b  = (const float*)d_in[19];
    float* out = (float*)d_out;

    __half *h1x, *h1g, *h2x, *h2g;
    float *xy; uint32_t *wq8, *wq11, *wq1;
    cudaGetSymbolAddress((void**)&h1x, g_h1x);
    cudaGetSymbolAddress((void**)&h1g, g_h1g);
    cudaGetSymbolAddress((void**)&h2x, g_h2x);
    cudaGetSymbolAddress((void**)&h2g, g_h2g);
    cudaGetSymbolAddress((void**)&xy, g_xy);
    cudaGetSymbolAddress((void**)&wq8, g_wq8);
    cudaGetSymbolAddress((void**)&wq11, g_wq11);
    cudaGetSymbolAddress((void**)&wq1, g_wq1);

    const size_t W8 = 9*8*2*32*4;
    const size_t W11 = 9*11*2*32*4;
    uint32_t* wq_fx2 = wq8;
    uint32_t* wq_fg2 = wq8 + W8;
    uint32_t* wq_c2  = wq8 + 2*W8;
    uint32_t* wq_fx3 = wq11;
    uint32_t* wq_fg3 = wq11 + W11;

    const int PIX_BLOCKS = Nn*HW/256;      // 4096
    const int C64_BLOCKS = Nn*64*8;        // 8192

    const int AH = 6*34*144;               // 29376
    const int SM64 = AH + 64*4;
    const int SM88 = AH + 88*4;
    const int SM8  = AH + 8*4;

    cudaFuncSetAttribute((const void*)conv64m<8, 64, 0, true>,
                         cudaFuncAttributeMaxDynamicSharedMemorySize, SM64);
    cudaFuncSetAttribute((const void*)conv64m<8, 64, 0, false>,
                         cudaFuncAttributeMaxDynamicSharedMemorySize, SM64);
    cudaFuncSetAttribute((const void*)conv64m<11, 81, 1, true>,
                         cudaFuncAttributeMaxDynamicSharedMemorySize, SM88);
    cudaFuncSetAttribute((const void*)conv64m<1, 1, 2, false>,
                         cudaFuncAttributeMaxDynamicSharedMemorySize, SM8);

    const int PQ8  = (9*8*2*32 + 255)/256;   // 18
    const int PQ11 = (9*11*2*32 + 255)/256;  // 25
    const int PQ1  = (9*1*2*32 + 255)/256;   // 3

    // ---- all weight prepacks up front (depend only on inputs) ----
    prepack_wq<8, 64><<<PQ8, 256>>>(fx_w2, wq_fx2);
    prepack_wq<8, 64><<<PQ8, 256>>>(fg_w2, wq_fg2);
    prepack_wq<8, 64><<<PQ8, 256>>>(c2_w,  wq_c2);
    prepack_wq<11, 81><<<PQ11, 256>>>(fx_w3, wq_fx3);
    prepack_wq<11, 81><<<PQ11, 256>>>(fg_w3, wq_fg3);
    prepack_wq<1, 1><<<PQ1, 256>>>(c3_w, wq1);

    // ---- batched x+g heads ----
    conv_in_small<1, true><<<2*PIX_BLOCKS, 256>>>(
        x, fx_w1, fx_b1, h1x, g, fg_w1, fg_b1, h1g);
    conv64m<8, 64, 0, true><<<2*C64_BLOCKS, 128, SM64>>>(
        h1x, wq_fx2, fx_b2, h2x, nullptr,
        h1g, wq_fg2, fg_b2, h2g, nullptr, nullptr);
    conv64m<11, 81, 1, true><<<2*C64_BLOCKS, 128, SM88>>>(
        h2x, wq_fx3, fx_b3, nullptr, x,
        h2g, wq_fg3, fg_b3, nullptr, g, xy);

    // ---- fusion head ----
    conv_in_small<2, false><<<PIX_BLOCKS, 256>>>(
        xy, c1_w, c1_b, h1x, nullptr, nullptr, nullptr, nullptr);
    conv64m<8, 64, 0, false><<<C64_BLOCKS, 128, SM64>>>(
        h1x, wq_c2, c2_b, h2x, nullptr,
        nullptr, nullptr, nullptr, nullptr, nullptr, nullptr);
    conv64m<1, 1, 2, false><<<C64_BLOCKS, 128, SM8>>>(
        h2x, wq1, c3_b, nullptr, nullptr,
        nullptr, nullptr, nullptr, nullptr, nullptr, out);
}

// round 14
// speedup vs baseline: 3.1041x; 1.0107x over previous
#include <cuda_runtime.h>
#include <cuda_fp16.h>
#include <cstdint>
#include <math.h>

#define Nn 16
#define Hh 256
#define Ww 256
#define HW (Hh*Ww)

// ---------------- scratch (device globals; no allocation allowed) ----------------
__device__ __half g_h1x[(size_t)Nn*HW*64];
__device__ __half g_h1g[(size_t)Nn*HW*64];
__device__ __half g_h2x[(size_t)Nn*HW*64];
__device__ __half g_h2g[(size_t)Nn*HW*64];
__device__ float g_xy[(size_t)Nn*2*HW];
__device__ __align__(16) uint32_t g_wq8[3][9*8*2*32*4];    // fx2, fg2, c2
__device__ __align__(16) uint32_t g_wq11[2][9*11*2*32*4];  // fx3, fg3
__device__ __align__(16) uint32_t g_wq1[9*1*2*32*4];       // c3

__device__ __forceinline__ void mma_f16(float* c, const uint32_t* a, uint32_t b0, uint32_t b1) {
    asm volatile("mma.sync.aligned.m16n8k16.row.col.f32.f16.f16.f32 "
        "{%0,%1,%2,%3},{%4,%5,%6,%7},{%8,%9},{%0,%1,%2,%3};"
        : "+f"(c[0]), "+f"(c[1]), "+f"(c[2]), "+f"(c[3])
        : "r"(a[0]), "r"(a[1]), "r"(a[2]), "r"(a[3]), "r"(b0), "r"(b1));
}
__device__ __forceinline__ void ldm_x4(uint32_t* r, uint32_t saddr) {
    asm volatile("ldmatrix.sync.aligned.m8n8.x4.shared.b16 {%0,%1,%2,%3}, [%4];"
        : "=r"(r[0]), "=r"(r[1]), "=r"(r[2]), "=r"(r[3]) : "r"(saddr));
}
__device__ __forceinline__ uint32_t pkh2(float a, float b) {
    return (uint32_t)__half_as_ushort(__float2half_rn(a)) |
           ((uint32_t)__half_as_ushort(__float2half_rn(b)) << 16);
}

// ------------- weight prepack (all convs, one launch) ----------------
// per-conv layout: [tap][nt][k2][lane] x uint4
__device__ __forceinline__ void pk_one(const float* __restrict__ w, uint32_t* __restrict__ o,
                                       int NT, int CO, int idx) {
    int lane = idx & 31;
    int k2 = (idx >> 5) & 1;
    int nt = (idx >> 6) % NT;
    int tap = idx / (64*NT);
    int lg = lane >> 2, lt = lane & 3;
    int co = nt*8 + lg;
    uint32_t r[4];
    #pragma unroll
    for (int kk = 0; kk < 2; kk++) {
        int c0 = (k2*2 + kk)*16 + lt*2;
        float v0 = (co < CO) ? w[((size_t)co*64 + c0)*9 + tap] : 0.f;
        float v1 = (co < CO) ? w[((size_t)co*64 + c0+1)*9 + tap] : 0.f;
        float v2 = (co < CO) ? w[((size_t)co*64 + c0+8)*9 + tap] : 0.f;
        float v3 = (co < CO) ? w[((size_t)co*64 + c0+9)*9 + tap] : 0.f;
        r[kk*2+0] = pkh2(v0, v1);
        r[kk*2+1] = pkh2(v2, v3);
    }
    ((uint4*)o)[idx] = make_uint4(r[0], r[1], r[2], r[3]);
}

__global__ void prepack_all(
    const float* fx2, const float* fg2, const float* c2,
    const float* fx3, const float* fg3, const float* c3,
    uint32_t* o8, uint32_t* o11, uint32_t* o1)
{
    const int S8 = 9*8*2*32;     // 4608
    const int S11 = 9*11*2*32;   // 6336
    const int S1 = 9*1*2*32;     // 576
    const size_t W8 = (size_t)S8*4, W11 = (size_t)S11*4;
    int idx = blockIdx.x * 256 + threadIdx.x;
    if (idx < S8) { pk_one(fx2, o8, 8, 64, idx); return; }
    idx -= S8;
    if (idx < S8) { pk_one(fg2, o8 + W8, 8, 64, idx); return; }
    idx -= S8;
    if (idx < S8) { pk_one(c2, o8 + 2*W8, 8, 64, idx); return; }
    idx -= S8;
    if (idx < S11) { pk_one(fx3, o11, 11, 81, idx); return; }
    idx -= S11;
    if (idx < S11) { pk_one(fg3, o11 + W11, 11, 81, idx); return; }
    idx -= S11;
    if (idx < S1) { pk_one(c3, o1, 1, 1, idx); return; }
}

// ---------------- conv 3x3, small Cin -> 64 relu, writes fp16 NHWC. Optional 2 heads. ----
// PIX_BLOCKS per head = 4096 = 2^12.
template<int CIN, bool DUAL>
__global__ __launch_bounds__(256) void conv_in_small(
    const float* __restrict__ in0, const float* __restrict__ w0, const float* __restrict__ b0,
    __half* __restrict__ oh0,
    const float* __restrict__ in1, const float* __restrict__ w1, const float* __restrict__ b1,
    __half* __restrict__ oh1)
{
    __shared__ float s_w[64*CIN*9];
    __shared__ float s_b[64];
    int tid = threadIdx.x;
    int head = DUAL ? (int)(blockIdx.x >> 12) : 0;
    const float* in = head ? in1 : in0;
    const float* w  = head ? w1 : w0;
    const float* b  = head ? b1 : b0;
    __half* oh      = head ? oh1 : oh0;

    for (int i = tid; i < 64*CIN*9; i += 256) s_w[i] = w[i];
    if (tid < 64) s_b[tid] = b[tid];
    __syncthreads();

    int px = (DUAL ? (int)(blockIdx.x & 4095) : (int)blockIdx.x)*256 + tid;
    int n = px >> 16; int rem = px & 65535;
    int y = rem >> 8;  int x = rem & 255;

    float iv[CIN*9];
    #pragma unroll
    for (int c = 0; c < CIN; c++)
        #pragma unroll
        for (int kh = 0; kh < 3; kh++)
            #pragma unroll
            for (int kw = 0; kw < 3; kw++) {
                int yy = y + kh - 1, xx = x + kw - 1;
                float v = 0.f;
                if (yy >= 0 && yy < Hh && xx >= 0 && xx < Ww)
                    v = in[((size_t)n*CIN + c)*HW + yy*Ww + xx];
                iv[c*9 + kh*3 + kw] = v;
            }

    float a[64];
    #pragma unroll
    for (int co = 0; co < 64; co++) {
        float s = s_b[co];
        #pragma unroll
        for (int i = 0; i < CIN*9; i++) s += s_w[co*CIN*9 + i] * iv[i];
        a[co] = fmaxf(s, 0.f);
    }

    char* ph = (char*)oh + (size_t)px * 128;
    #pragma unroll
    for (int q = 0; q < 8; q++) {
        uint32_t hw[4];
        #pragma unroll
        for (int t = 0; t < 4; t++)
            hw[t] = pkh2(a[q*8 + t*2], a[q*8 + t*2 + 1]);
        *(uint4*)(ph + q*16) = make_uint4(hw[0], hw[1], hw[2], hw[3]);
    }
}

// ---------------- mma.sync conv 3x3, 64 -> CO, fp16, single pass. -------------------
// CTA tile: 4 y-rows x 32 x (M=128). A tile: 6 rows x 34 px x 144B = 29376 B.
// MODE: 0 = bias+relu -> fp16 NHWC; 1 = fused softmax+9x9 filter -> xy (fsrc window in smem);
//       2 = bias -> fp32 planar (channel 0 only)
// Blocks per head = 16n x 64yq x 8xq = 8192 = 2^13.
template<int NT, int CO, int MODE, bool DUAL>
__global__ __launch_bounds__(128, (NT == 1) ? 5 : ((NT == 8) ? 4 : 3)) void conv64m(
    const __half* __restrict__ ih0, const uint32_t* __restrict__ wq0,
    const float* __restrict__ bias0, __half* __restrict__ oh0, const float* __restrict__ fsrc0,
    const __half* __restrict__ ih1, const uint32_t* __restrict__ wq1,
    const float* __restrict__ bias1, __half* __restrict__ oh1, const float* __restrict__ fsrc1,
    float* __restrict__ xy)
{
    constexpr int CP = NT * 8;
    constexpr int AH = 6*34*144;          // 29376 bytes
    extern __shared__ char sm[];
    char* sA = sm;
    float* s_bias = (float*)(sm + AH);
    float* sF = s_bias + CP;              // MODE1: 12 x 40 fp32 zero-padded window

    int tid = threadIdx.x;
    int lane = tid & 31, wid = tid >> 5;
    int lg = lane >> 2, lt = lane & 3;
    int py = wid;                         // warp = one y-row

    int bid = blockIdx.x;
    int head = DUAL ? (bid >> 13) : 0;
    bid &= 8191;                          // 16n x 64yq x 8xq
    const __half* ih = head ? ih1 : ih0;
    const uint32_t* wq = head ? wq1 : wq0;
    const float* bias = head ? bias1 : bias0;
    __half* oh = head ? oh1 : oh0;
    const float* fsrc = head ? fsrc1 : fsrc0;

    int xq = bid & 7;
    int yq = (bid >> 3) & 63;
    int n  = bid >> 9;
    int y0 = yq * 4, x0 = xq * 32;
    size_t nbase = (size_t)n * 65536;

    if (tid < CP) s_bias[tid] = (tid < CO) ? bias[tid] : 0.f;

    // stage A tile from fp16 global (zero halo = conv zero-padding)
    for (int idx = tid; idx < 6*34*8; idx += 128) {
        int c = idx & 7, e = idx >> 3;
        int row = e / 34, px = e - row*34;
        int gy = y0 + row - 1, gx = x0 + px - 1;
        uint4 vh = make_uint4(0,0,0,0);
        if ((unsigned)gy < 256u && (unsigned)gx < 256u)
            vh = *(const uint4*)((const char*)ih + (nbase + gy*256 + gx)*128 + c*16);
        *(uint4*)(sA + (row*34 + px)*144 + c*16) = vh;
    }
    if constexpr (MODE == 1) {
        // stage 9x9 filter source window: rows y0-4..y0+7, cols x0-4..x0+35 (12x40)
        const float* sp = fsrc + nbase;
        for (int idx = tid; idx < 12*40; idx += 128) {
            int row = idx / 40, col = idx - row*40;
            int gy = y0 - 4 + row, gx = x0 - 4 + col;
            float v = 0.f;
            if ((unsigned)gy < 256u && (unsigned)gx < 256u)
                v = sp[gy*256 + gx];
            sF[idx] = v;
        }
    }
    __syncthreads();

    float acc[2][NT][4];
    #pragma unroll
    for (int mt = 0; mt < 2; mt++)
        #pragma unroll
        for (int nt = 0; nt < NT; nt++)
            #pragma unroll
            for (int j = 0; j < 4; j++) acc[mt][nt][j] = 0.f;

    uint32_t sA_s = (uint32_t)__cvta_generic_to_shared(sA);
    uint32_t rbase = (uint32_t)((lane & 15) * 144 + ((lane >> 4) << 4));
    const uint4* wq4 = (const uint4*)wq;

    #pragma unroll 1
    for (int tap = 0; tap < 9; tap++) {
        int kh = tap / 3, kw = tap - kh*3;
        uint32_t base0 = sA_s + (uint32_t)(((py + kh)*34 + kw)*144) + rbase;
        const uint4* wt = wq4 + (size_t)tap*NT*2*32 + lane;
        #pragma unroll
        for (int k2 = 0; k2 < 2; k2++) {
            uint32_t ah[2][2][4];   // [kk][mt][4]
            #pragma unroll
            for (int kk = 0; kk < 2; kk++)
                #pragma unroll
                for (int mt = 0; mt < 2; mt++)
                    ldm_x4(ah[kk][mt], base0 + mt*2304 + (k2*2 + kk)*32);
            #pragma unroll
            for (int nt = 0; nt < NT; nt++) {
                uint4 bb = wt[(nt*2 + k2)*32];
                #pragma unroll
                for (int mt = 0; mt < 2; mt++) {
                    mma_f16(acc[mt][nt], ah[0][mt], bb.x, bb.y);
                    mma_f16(acc[mt][nt], ah[1][mt], bb.z, bb.w);
                }
            }
        }
    }

    int Y = y0 + py;
    if constexpr (MODE == 0) {
        // bias + relu + fp16 global
        #pragma unroll
        for (int mt = 0; mt < 2; mt++) {
            size_t pix0 = nbase + (size_t)Y*256 + x0 + mt*16 + lg;
            #pragma unroll
            for (int nt = 0; nt < NT; nt++) {
                int co = nt*8 + lt*2;
                float b0 = s_bias[co], b1v = s_bias[co+1];
                *(uint32_t*)((char*)oh + pix0*128 + co*2) =
                    pkh2(fmaxf(acc[mt][nt][0] + b0, 0.f), fmaxf(acc[mt][nt][1] + b1v, 0.f));
                *(uint32_t*)((char*)oh + (pix0+8)*128 + co*2) =
                    pkh2(fmaxf(acc[mt][nt][2] + b0, 0.f), fmaxf(acc[mt][nt][3] + b1v, 0.f));
            }
        }
    } else if constexpr (MODE == 1) {
        // fused softmax over 81 logits + 9x9 pixel-adaptive filtering (window in smem)
        #pragma unroll
        for (int mt = 0; mt < 2; mt++) {
            #pragma unroll
            for (int r = 0; r < 2; r++) {
                int xw = mt*16 + lg + r*8;        // window-local x (0..31)
                float v[NT][2];
                float mx = -1e30f;
                #pragma unroll
                for (int nt = 0; nt < NT; nt++) {
                    #pragma unroll
                    for (int j = 0; j < 2; j++) {
                        int co = nt*8 + lt*2 + j;
                        v[nt][j] = acc[mt][nt][r*2 + j] + s_bias[co];
                        if (co < 81) mx = fmaxf(mx, v[nt][j]);
                    }
                }
                mx = fmaxf(mx, __shfl_xor_sync(0xffffffffu, mx, 1));
                mx = fmaxf(mx, __shfl_xor_sync(0xffffffffu, mx, 2));
                float se = 0.f, fo = 0.f;
                #pragma unroll
                for (int nt = 0; nt < NT; nt++) {
                    #pragma unroll
                    for (int j = 0; j < 2; j++) {
                        int co = nt*8 + lt*2 + j;
                        if (co < 81) {
                            float e = __expf(v[nt][j] - mx);
                            se += e;
                            int kh = co / 9, kw = co - kh*9;
                            fo += e * sF[(py + kh)*40 + xw + kw];
                        }
                    }
                }
                se += __shfl_xor_sync(0xffffffffu, se, 1);
                se += __shfl_xor_sync(0xffffffffu, se, 2);
                fo += __shfl_xor_sync(0xffffffffu, fo, 1);
                fo += __shfl_xor_sync(0xffffffffu, fo, 2);
                if (lt == 0)
                    xy[((size_t)n*2 + head)*HW + Y*256 + x0 + xw] = fo / se;
            }
        }
    } else {
        // MODE 2: fp32 planar out, channel 0 only
        float b0 = s_bias[0];
        if (lt == 0) {
            #pragma unroll
            for (int mt = 0; mt < 2; mt++)
                #pragma unroll
                for (int r = 0; r < 2; r++) {
                    int X = x0 + mt*16 + lg + r*8;
                    xy[nbase + (size_t)Y*256 + X] = acc[mt][0][r*2] + b0;
                }
        }
    }
}

// ---------------- launch ----------------
extern "C" void kernel_launch(void* const* d_in, const int* in_sizes, int n_in,
                              void* d_out, int out_size)
{
    const float* x     = (const float*)d_in[0];
    const float* g     = (const float*)d_in[1];
    const float* fx_w1 = (const float*)d_in[2];
    const float* fx_b1 = (const float*)d_in[3];
    const float* fx_w2 = (const float*)d_in[4];
    const float* fx_b2 = (const float*)d_in[5];
    const float* fx_w3 = (const float*)d_in[6];
    const float* fx_b3 = (const float*)d_in[7];
    const float* fg_w1 = (const float*)d_in[8];
    const float* fg_b1 = (const float*)d_in[9];
    const float* fg_w2 = (const float*)d_in[10];
    const float* fg_b2 = (const float*)d_in[11];
    const float* fg_w3 = (const float*)d_in[12];
    const float* fg_b3 = (const float*)d_in[13];
    const float* c1_w  = (const float*)d_in[14];
    const float* c1_b  = (const float*)d_in[15];
    const float* c2_w  = (const float*)d_in[16];
    const float* c2_b  = (const float*)d_in[17];
    const float* c3_w  = (const float*)d_in[18];
    const float* c3_b  = (const float*)d_in[19];
    float* out = (float*)d_out;

    __half *h1x, *h1g, *h2x, *h2g;
    float *xy; uint32_t *wq8, *wq11, *wq1;
    cudaGetSymbolAddress((void**)&h1x, g_h1x);
    cudaGetSymbolAddress((void**)&h1g, g_h1g);
    cudaGetSymbolAddress((void**)&h2x, g_h2x);
    cudaGetSymbolAddress((void**)&h2g, g_h2g);
    cudaGetSymbolAddress((void**)&xy, g_xy);
    cudaGetSymbolAddress((void**)&wq8, g_wq8);
    cudaGetSymbolAddress((void**)&wq11, g_wq11);
    cudaGetSymbolAddress((void**)&wq1, g_wq1);

    const size_t W8 = 9*8*2*32*4;
    const size_t W11 = 9*11*2*32*4;
    uint32_t* wq_fx2 = wq8;
    uint32_t* wq_fg2 = wq8 + W8;
    uint32_t* wq_c2  = wq8 + 2*W8;
    uint32_t* wq_fx3 = wq11;
    uint32_t* wq_fg3 = wq11 + W11;

    const int PIX_BLOCKS = Nn*HW/256;      // 4096
    const int C64_BLOCKS = Nn*64*8;        // 8192

    const int AH = 6*34*144;               // 29376
    const int SM64 = AH + 64*4;
    const int SM88 = AH + 88*4 + 12*40*4;  // + filter window
    const int SM8  = AH + 8*4;

    cudaFuncSetAttribute((const void*)conv64m<8, 64, 0, true>,
                         cudaFuncAttributeMaxDynamicSharedMemorySize, SM64);
    cudaFuncSetAttribute((const void*)conv64m<8, 64, 0, false>,
                         cudaFuncAttributeMaxDynamicSharedMemorySize, SM64);
    cudaFuncSetAttribute((const void*)conv64m<11, 81, 1, true>,
                         cudaFuncAttributeMaxDynamicSharedMemorySize, SM88);
    cudaFuncSetAttribute((const void*)conv64m<1, 1, 2, false>,
                         cudaFuncAttributeMaxDynamicSharedMemorySize, SM8);

    // ---- single fused weight prepack ----
    const int PK_TOTAL = 3*(9*8*2*32) + 2*(9*11*2*32) + 9*1*2*32;  // 27072
    prepack_all<<<(PK_TOTAL + 255)/256, 256>>>(
        fx_w2, fg_w2, c2_w, fx_w3, fg_w3, c3_w, wq8, wq11, wq1);

    // ---- batched x+g heads ----
    conv_in_small<1, true><<<2*PIX_BLOCKS, 256>>>(
        x, fx_w1, fx_b1, h1x, g, fg_w1, fg_b1, h1g);
    conv64m<8, 64, 0, true><<<2*C64_BLOCKS, 128, SM64>>>(
        h1x, wq_fx2, fx_b2, h2x, nullptr,
        h1g, wq_fg2, fg_b2, h2g, nullptr, nullptr);
    conv64m<11, 81, 1, true><<<2*C64_BLOCKS, 128, SM88>>>(
        h2x, wq_fx3, fx_b3, nullptr, x,
        h2g, wq_fg3, fg_b3, nullptr, g, xy);

    // ---- fusion head ----
    conv_in_small<2, false><<<PIX_BLOCKS, 256>>>(
        xy, c1_w, c1_b, h1x, nullptr, nullptr, nullptr, nullptr);
    conv64m<8, 64, 0, false><<<C64_BLOCKS, 128, SM64>>>(
        h1x, wq_c2, c2_b, h2x, nullptr,
        nullptr, nullptr, nullptr, nullptr, nullptr, nullptr);
    conv64m<1, 1, 2, false><<<C64_BLOCKS, 128, SM8>>>(
        h2x, wq1, c3_b, nullptr, nullptr,
        nullptr, nullptr, nullptr, nullptr, nullptr, out);
}

// round 15
// speedup vs baseline: 3.1480x; 1.0141x over previous
#include <cuda_runtime.h>
#include <cuda_fp16.h>
#include <cstdint>
#include <math.h>

#define Nn 16
#define Hh 256
#define Ww 256
#define HW (Hh*Ww)

// ---------------- scratch (device globals; no allocation allowed) ----------------
__device__ __half g_h1x[(size_t)Nn*HW*64];
__device__ __half g_h1g[(size_t)Nn*HW*64];
__device__ __half g_h2x[(size_t)Nn*HW*64];
__device__ __half g_h2g[(size_t)Nn*HW*64];
__device__ float g_xy[(size_t)Nn*2*HW];
__device__ __align__(16) uint32_t g_wq8[3][9*8*2*32*4];    // fx2, fg2, c2
__device__ __align__(16) uint32_t g_wq11[2][9*11*2*32*4];  // fx3, fg3
__device__ __align__(16) uint32_t g_wq1[9*1*2*32*4];       // c3

__device__ __forceinline__ void mma_f16(float* c, const uint32_t* a, uint32_t b0, uint32_t b1) {
    asm volatile("mma.sync.aligned.m16n8k16.row.col.f32.f16.f16.f32 "
        "{%0,%1,%2,%3},{%4,%5,%6,%7},{%8,%9},{%0,%1,%2,%3};"
        : "+f"(c[0]), "+f"(c[1]), "+f"(c[2]), "+f"(c[3])
        : "r"(a[0]), "r"(a[1]), "r"(a[2]), "r"(a[3]), "r"(b0), "r"(b1));
}
__device__ __forceinline__ void ldm_x4(uint32_t* r, uint32_t saddr) {
    asm volatile("ldmatrix.sync.aligned.m8n8.x4.shared.b16 {%0,%1,%2,%3}, [%4];"
        : "=r"(r[0]), "=r"(r[1]), "=r"(r[2]), "=r"(r[3]) : "r"(saddr));
}
__device__ __forceinline__ uint32_t pkh2(float a, float b) {
    return (uint32_t)__half_as_ushort(__float2half_rn(a)) |
           ((uint32_t)__half_as_ushort(__float2half_rn(b)) << 16);
}

// ------------- weight prepack (all convs, one launch) ----------------
// per-conv layout: [tap][nt][k2][lane] x uint4
__device__ __forceinline__ void pk_one(const float* __restrict__ w, uint32_t* __restrict__ o,
                                       int NT, int CO, int idx) {
    int lane = idx & 31;
    int k2 = (idx >> 5) & 1;
    int nt = (idx >> 6) % NT;
    int tap = idx / (64*NT);
    int lg = lane >> 2, lt = lane & 3;
    int co = nt*8 + lg;
    uint32_t r[4];
    #pragma unroll
    for (int kk = 0; kk < 2; kk++) {
        int c0 = (k2*2 + kk)*16 + lt*2;
        float v0 = (co < CO) ? w[((size_t)co*64 + c0)*9 + tap] : 0.f;
        float v1 = (co < CO) ? w[((size_t)co*64 + c0+1)*9 + tap] : 0.f;
        float v2 = (co < CO) ? w[((size_t)co*64 + c0+8)*9 + tap] : 0.f;
        float v3 = (co < CO) ? w[((size_t)co*64 + c0+9)*9 + tap] : 0.f;
        r[kk*2+0] = pkh2(v0, v1);
        r[kk*2+1] = pkh2(v2, v3);
    }
    ((uint4*)o)[idx] = make_uint4(r[0], r[1], r[2], r[3]);
}

__global__ void prepack_all(
    const float* fx2, const float* fg2, const float* c2,
    const float* fx3, const float* fg3, const float* c3,
    uint32_t* o8, uint32_t* o11, uint32_t* o1)
{
    const int S8 = 9*8*2*32;     // 4608
    const int S11 = 9*11*2*32;   // 6336
    const int S1 = 9*1*2*32;     // 576
    const size_t W8 = (size_t)S8*4, W11 = (size_t)S11*4;
    int idx = blockIdx.x * 256 + threadIdx.x;
    if (idx < S8) { pk_one(fx2, o8, 8, 64, idx); return; }
    idx -= S8;
    if (idx < S8) { pk_one(fg2, o8 + W8, 8, 64, idx); return; }
    idx -= S8;
    if (idx < S8) { pk_one(c2, o8 + 2*W8, 8, 64, idx); return; }
    idx -= S8;
    if (idx < S11) { pk_one(fx3, o11, 11, 81, idx); return; }
    idx -= S11;
    if (idx < S11) { pk_one(fg3, o11 + W11, 11, 81, idx); return; }
    idx -= S11;
    if (idx < S1) { pk_one(c3, o1, 1, 1, idx); return; }
}

// ---------------- conv 3x3, small Cin -> 64 relu, writes fp16 NHWC. Optional 2 heads. ----
// PIX_BLOCKS per head = 4096 = 2^12.
template<int CIN, bool DUAL>
__global__ __launch_bounds__(256) void conv_in_small(
    const float* __restrict__ in0, const float* __restrict__ w0, const float* __restrict__ b0,
    __half* __restrict__ oh0,
    const float* __restrict__ in1, const float* __restrict__ w1, const float* __restrict__ b1,
    __half* __restrict__ oh1)
{
    __shared__ float s_w[64*CIN*9];
    __shared__ float s_b[64];
    int tid = threadIdx.x;
    int head = DUAL ? (int)(blockIdx.x >> 12) : 0;
    const float* in = head ? in1 : in0;
    const float* w  = head ? w1 : w0;
    const float* b  = head ? b1 : b0;
    __half* oh      = head ? oh1 : oh0;

    for (int i = tid; i < 64*CIN*9; i += 256) s_w[i] = w[i];
    if (tid < 64) s_b[tid] = b[tid];
    __syncthreads();

    int px = (DUAL ? (int)(blockIdx.x & 4095) : (int)blockIdx.x)*256 + tid;
    int n = px >> 16; int rem = px & 65535;
    int y = rem >> 8;  int x = rem & 255;

    float iv[CIN*9];
    #pragma unroll
    for (int c = 0; c < CIN; c++)
        #pragma unroll
        for (int kh = 0; kh < 3; kh++)
            #pragma unroll
            for (int kw = 0; kw < 3; kw++) {
                int yy = y + kh - 1, xx = x + kw - 1;
                float v = 0.f;
                if (yy >= 0 && yy < Hh && xx >= 0 && xx < Ww)
                    v = in[((size_t)n*CIN + c)*HW + yy*Ww + xx];
                iv[c*9 + kh*3 + kw] = v;
            }

    float a[64];
    #pragma unroll
    for (int co = 0; co < 64; co++) {
        float s = s_b[co];
        #pragma unroll
        for (int i = 0; i < CIN*9; i++) s += s_w[co*CIN*9 + i] * iv[i];
        a[co] = fmaxf(s, 0.f);
    }

    char* ph = (char*)oh + (size_t)px * 128;
    #pragma unroll
    for (int q = 0; q < 8; q++) {
        uint32_t hw[4];
        #pragma unroll
        for (int t = 0; t < 4; t++)
            hw[t] = pkh2(a[q*8 + t*2], a[q*8 + t*2 + 1]);
        *(uint4*)(ph + q*16) = make_uint4(hw[0], hw[1], hw[2], hw[3]);
    }
}

// ---------------- mma.sync conv 3x3, 64 -> CO, fp16, single pass. -------------------
// CTA tile: 8 y-rows x 32 x (M=256). Warp: 2 y-rows x 32 px = 4 m16 tiles (mt = r*2+h).
// A tile: 10 rows x 34 px x 144B = 48960 B.
// MODE: 0 = bias+relu -> fp16 NHWC; 1 = fused softmax+9x9 filter -> xy (window in smem);
//       2 = bias -> fp32 planar (channel 0 only)
// Blocks per head = 16n x 32yq x 8xq = 4096 = 2^12.
template<int NT, int CO, int MODE, bool DUAL>
__global__ __launch_bounds__(128, 2) void conv64m(
    const __half* __restrict__ ih0, const uint32_t* __restrict__ wq0,
    const float* __restrict__ bias0, __half* __restrict__ oh0, const float* __restrict__ fsrc0,
    const __half* __restrict__ ih1, const uint32_t* __restrict__ wq1,
    const float* __restrict__ bias1, __half* __restrict__ oh1, const float* __restrict__ fsrc1,
    float* __restrict__ xy)
{
    constexpr int CP = NT * 8;
    constexpr int AH = 10*34*144;         // 48960 bytes
    extern __shared__ char sm[];
    char* sA = sm;
    float* s_bias = (float*)(sm + AH);
    float* sF = s_bias + CP;              // MODE1: 16 x 40 fp32 zero-padded window

    int tid = threadIdx.x;
    int lane = tid & 31, wid = tid >> 5;
    int lg = lane >> 2, lt = lane & 3;

    int bid = blockIdx.x;
    int head = DUAL ? (bid >> 12) : 0;
    bid &= 4095;                          // 16n x 32yq x 8xq
    const __half* ih = head ? ih1 : ih0;
    const uint32_t* wq = head ? wq1 : wq0;
    const float* bias = head ? bias1 : bias0;
    __half* oh = head ? oh1 : oh0;
    const float* fsrc = head ? fsrc1 : fsrc0;

    int xq = bid & 7;
    int yq = (bid >> 3) & 31;
    int n  = bid >> 8;
    int y0 = yq * 8, x0 = xq * 32;
    size_t nbase = (size_t)n * 65536;

    if (tid < CP) s_bias[tid] = (tid < CO) ? bias[tid] : 0.f;

    // stage A tile from fp16 global (zero halo = conv zero-padding)
    for (int idx = tid; idx < 10*34*8; idx += 128) {
        int c = idx & 7, e = idx >> 3;
        int row = e / 34, px = e - row*34;
        int gy = y0 + row - 1, gx = x0 + px - 1;
        uint4 vh = make_uint4(0,0,0,0);
        if ((unsigned)gy < 256u && (unsigned)gx < 256u)
            vh = *(const uint4*)((const char*)ih + (nbase + gy*256 + gx)*128 + c*16);
        *(uint4*)(sA + (row*34 + px)*144 + c*16) = vh;
    }
    if constexpr (MODE == 1) {
        // stage 9x9 filter source window: rows y0-4..y0+11, cols x0-4..x0+35 (16x40)
        const float* sp = fsrc + nbase;
        for (int idx = tid; idx < 16*40; idx += 128) {
            int row = idx / 40, col = idx - row*40;
            int gy = y0 - 4 + row, gx = x0 - 4 + col;
            float v = 0.f;
            if ((unsigned)gy < 256u && (unsigned)gx < 256u)
                v = sp[gy*256 + gx];
            sF[idx] = v;
        }
    }
    __syncthreads();

    float acc[4][NT][4];
    #pragma unroll
    for (int mt = 0; mt < 4; mt++)
        #pragma unroll
        for (int nt = 0; nt < NT; nt++)
            #pragma unroll
            for (int j = 0; j < 4; j++) acc[mt][nt][j] = 0.f;

    uint32_t sA_s = (uint32_t)__cvta_generic_to_shared(sA);
    uint32_t rbase = (uint32_t)((lane & 15) * 144 + ((lane >> 4) << 4));
    const uint4* wq4 = (const uint4*)wq;

    #pragma unroll 1
    for (int tap = 0; tap < 9; tap++) {
        int kh = tap / 3, kw = tap - kh*3;
        const uint4* wt = wq4 + (size_t)tap*NT*2*32 + lane;
        #pragma unroll
        for (int k2 = 0; k2 < 2; k2++) {
            uint32_t ah[2][4][4];   // [kk][mt][4], mt = r*2 + h
            #pragma unroll
            for (int kk = 0; kk < 2; kk++)
                #pragma unroll
                for (int r = 0; r < 2; r++)
                    #pragma unroll
                    for (int h = 0; h < 2; h++) {
                        uint32_t ad = sA_s +
                            (uint32_t)(((wid*2 + r + kh)*34 + h*16 + kw)*144) +
                            rbase + (k2*2 + kk)*32;
                        ldm_x4(ah[kk][r*2 + h], ad);
                    }
            #pragma unroll
            for (int nt = 0; nt < NT; nt++) {
                uint4 bb = wt[(nt*2 + k2)*32];
                #pragma unroll
                for (int mt = 0; mt < 4; mt++) {
                    mma_f16(acc[mt][nt], ah[0][mt], bb.x, bb.y);
                    mma_f16(acc[mt][nt], ah[1][mt], bb.z, bb.w);
                }
            }
        }
    }

    if constexpr (MODE == 0) {
        // bias + relu + fp16 global
        #pragma unroll
        for (int mt = 0; mt < 4; mt++) {
            int r = mt >> 1, h = mt & 1;
            int Y = y0 + wid*2 + r;
            size_t pix0 = nbase + (size_t)Y*256 + x0 + h*16 + lg;
            #pragma unroll
            for (int nt = 0; nt < NT; nt++) {
                int co = nt*8 + lt*2;
                float b0 = s_bias[co], b1v = s_bias[co+1];
                *(uint32_t*)((char*)oh + pix0*128 + co*2) =
                    pkh2(fmaxf(acc[mt][nt][0] + b0, 0.f), fmaxf(acc[mt][nt][1] + b1v, 0.f));
                *(uint32_t*)((char*)oh + (pix0+8)*128 + co*2) =
                    pkh2(fmaxf(acc[mt][nt][2] + b0, 0.f), fmaxf(acc[mt][nt][3] + b1v, 0.f));
            }
        }
    } else if constexpr (MODE == 1) {
        // fused softmax over 81 logits + 9x9 pixel-adaptive filtering (window in smem)
        #pragma unroll
        for (int mt = 0; mt < 4; mt++) {
            int r = mt >> 1, h = mt & 1;
            int yw = wid*2 + r;                   // window-local y
            #pragma unroll
            for (int rr = 0; rr < 2; rr++) {
                int xw = h*16 + lg + rr*8;        // window-local x (0..31)
                float v[NT][2];
                float mx = -1e30f;
                #pragma unroll
                for (int nt = 0; nt < NT; nt++) {
                    #pragma unroll
                    for (int j = 0; j < 2; j++) {
                        int co = nt*8 + lt*2 + j;
                        v[nt][j] = acc[mt][nt][rr*2 + j] + s_bias[co];
                        if (co < 81) mx = fmaxf(mx, v[nt][j]);
                    }
                }
                mx = fmaxf(mx, __shfl_xor_sync(0xffffffffu, mx, 1));
                mx = fmaxf(mx, __shfl_xor_sync(0xffffffffu, mx, 2));
                float se = 0.f, fo = 0.f;
                #pragma unroll
                for (int nt = 0; nt < NT; nt++) {
                    #pragma unroll
                    for (int j = 0; j < 2; j++) {
                        int co = nt*8 + lt*2 + j;
                        if (co < 81) {
                            float e = __expf(v[nt][j] - mx);
                            se += e;
                            int kh = co / 9, kw = co - kh*9;
                            fo += e * sF[(yw + kh)*40 + xw + kw];
                        }
                    }
                }
                se += __shfl_xor_sync(0xffffffffu, se, 1);
                se += __shfl_xor_sync(0xffffffffu, se, 2);
                fo += __shfl_xor_sync(0xffffffffu, fo, 1);
                fo += __shfl_xor_sync(0xffffffffu, fo, 2);
                if (lt == 0)
                    xy[((size_t)n*2 + head)*HW + (y0 + yw)*256 + x0 + xw] = fo / se;
            }
        }
    } else {
        // MODE 2: fp32 planar out, channel 0 only
        float b0 = s_bias[0];
        if (lt == 0) {
            #pragma unroll
            for (int mt = 0; mt < 4; mt++) {
                int r = mt >> 1, h = mt & 1;
                int Y = y0 + wid*2 + r;
                #pragma unroll
                for (int rr = 0; rr < 2; rr++) {
                    int X = x0 + h*16 + lg + rr*8;
                    xy[nbase + (size_t)Y*256 + X] = acc[mt][0][rr*2] + b0;
                }
            }
        }
    }
}

// ---------------- launch ----------------
extern "C" void kernel_launch(void* const* d_in, const int* in_sizes, int n_in,
                              void* d_out, int out_size)
{
    const float* x     = (const float*)d_in[0];
    const float* g     = (const float*)d_in[1];
    const float* fx_w1 = (const float*)d_in[2];
    const float* fx_b1 = (const float*)d_in[3];
    const float* fx_w2 = (const float*)d_in[4];
    const float* fx_b2 = (const float*)d_in[5];
    const float* fx_w3 = (const float*)d_in[6];
    const float* fx_b3 = (const float*)d_in[7];
    const float* fg_w1 = (const float*)d_in[8];
    const float* fg_b1 = (const float*)d_in[9];
    const float* fg_w2 = (const float*)d_in[10];
    const float* fg_b2 = (const float*)d_in[11];
    const float* fg_w3 = (const float*)d_in[12];
    const float* fg_b3 = (const float*)d_in[13];
    const float* c1_w  = (const float*)d_in[14];
    const float* c1_b  = (const float*)d_in[15];
    const float* c2_w  = (const float*)d_in[16];
    const float* c2_b  = (const float*)d_in[17];
    const float* c3_w  = (const float*)d_in[18];
    const float* c3_b  = (const float*)d_in[19];
    float* out = (float*)d_out;

    __half *h1x, *h1g, *h2x, *h2g;
    float *xy; uint32_t *wq8, *wq11, *wq1;
    cudaGetSymbolAddress((void**)&h1x, g_h1x);
    cudaGetSymbolAddress((void**)&h1g, g_h1g);
    cudaGetSymbolAddress((void**)&h2x, g_h2x);
    cudaGetSymbolAddress((void**)&h2g, g_h2g);
    cudaGetSymbolAddress((void**)&xy, g_xy);
    cudaGetSymbolAddress((void**)&wq8, g_wq8);
    cudaGetSymbolAddress((void**)&wq11, g_wq11);
    cudaGetSymbolAddress((void**)&wq1, g_wq1);

    const size_t W8 = 9*8*2*32*4;
    const size_t W11 = 9*11*2*32*4;
    uint32_t* wq_fx2 = wq8;
    uint32_t* wq_fg2 = wq8 + W8;
    uint32_t* wq_c2  = wq8 + 2*W8;
    uint32_t* wq_fx3 = wq11;
    uint32_t* wq_fg3 = wq11 + W11;

    const int PIX_BLOCKS = Nn*HW/256;      // 4096
    const int C64_BLOCKS = Nn*32*8;        // 4096

    const int AH = 10*34*144;              // 48960
    const int SM64 = AH + 64*4;
    const int SM88 = AH + 88*4 + 16*40*4;  // + filter window
    const int SM8  = AH + 8*4;

    cudaFuncSetAttribute((const void*)conv64m<8, 64, 0, true>,
                         cudaFuncAttributeMaxDynamicSharedMemorySize, SM64);
    cudaFuncSetAttribute((const void*)conv64m<8, 64, 0, false>,
                         cudaFuncAttributeMaxDynamicSharedMemorySize, SM64);
    cudaFuncSetAttribute((const void*)conv64m<11, 81, 1, true>,
                         cudaFuncAttributeMaxDynamicSharedMemorySize, SM88);
    cudaFuncSetAttribute((const void*)conv64m<1, 1, 2, false>,
                         cudaFuncAttributeMaxDynamicSharedMemorySize, SM8);

    // ---- single fused weight prepack ----
    const int PK_TOTAL = 3*(9*8*2*32) + 2*(9*11*2*32) + 9*1*2*32;  // 27072
    prepack_all<<<(PK_TOTAL + 255)/256, 256>>>(
        fx_w2, fg_w2, c2_w, fx_w3, fg_w3, c3_w, wq8, wq11, wq1);

    // ---- batched x+g heads ----
    conv_in_small<1, true><<<2*PIX_BLOCKS, 256>>>(
        x, fx_w1, fx_b1, h1x, g, fg_w1, fg_b1, h1g);
    conv64m<8, 64, 0, true><<<2*C64_BLOCKS, 128, SM64>>>(
        h1x, wq_fx2, fx_b2, h2x, nullptr,
        h1g, wq_fg2, fg_b2, h2g, nullptr, nullptr);
    conv64m<11, 81, 1, true><<<2*C64_BLOCKS, 128, SM88>>>(
        h2x, wq_fx3, fx_b3, nullptr, x,
        h2g, wq_fg3, fg_b3, nullptr, g, xy);

    // ---- fusion head ----
    conv_in_small<2, false><<<PIX_BLOCKS, 256>>>(
        xy, c1_w, c1_b, h1x, nullptr, nullptr, nullptr, nullptr);
    conv64m<8, 64, 0, false><<<C64_BLOCKS, 128, SM64>>>(
        h1x, wq_c2, c2_b, h2x, nullptr,
        nullptr, nullptr, nullptr, nullptr, nullptr, nullptr);
    conv64m<1, 1, 2, false><<<C64_BLOCKS, 128, SM8>>>(
        h2x, wq1, c3_b, nullptr, nullptr,
        nullptr, nullptr, nullptr, nullptr, nullptr, out);
}

// round 16
// speedup vs baseline: 3.7151x; 1.1801x over previous
#include <cuda_runtime.h>
#include <cuda_fp16.h>
#include <cstdint>
#include <math.h>

#define Nn 16
#define Hh 256
#define Ww 256
#define HW (Hh*Ww)

// ---------------- scratch (device globals; no allocation allowed) ----------------
__device__ __half g_h1x[(size_t)Nn*HW*64];
__device__ __half g_h1g[(size_t)Nn*HW*64];
__device__ __half g_h2x[(size_t)Nn*HW*64];
__device__ __half g_h2g[(size_t)Nn*HW*64];
__device__ float g_xy[(size_t)Nn*2*HW];
__device__ __align__(16) uint32_t g_wq8[3][9*8*2*32*4];    // fx2, fg2, c2
__device__ __align__(16) uint32_t g_wq11[2][9*11*2*32*4];  // fx3, fg3
__device__ __align__(16) uint32_t g_wq1[9*1*2*32*4];       // c3

__device__ __forceinline__ void mma_f16(float* c, const uint32_t* a, uint32_t b0, uint32_t b1) {
    asm volatile("mma.sync.aligned.m16n8k16.row.col.f32.f16.f16.f32 "
        "{%0,%1,%2,%3},{%4,%5,%6,%7},{%8,%9},{%0,%1,%2,%3};"
        : "+f"(c[0]), "+f"(c[1]), "+f"(c[2]), "+f"(c[3])
        : "r"(a[0]), "r"(a[1]), "r"(a[2]), "r"(a[3]), "r"(b0), "r"(b1));
}
__device__ __forceinline__ void ldm_x4(uint32_t* r, uint32_t saddr) {
    asm volatile("ldmatrix.sync.aligned.m8n8.x4.shared.b16 {%0,%1,%2,%3}, [%4];"
        : "=r"(r[0]), "=r"(r[1]), "=r"(r[2]), "=r"(r[3]) : "r"(saddr));
}
__device__ __forceinline__ uint32_t pkh2(float a, float b) {
    return (uint32_t)__half_as_ushort(__float2half_rn(a)) |
           ((uint32_t)__half_as_ushort(__float2half_rn(b)) << 16);
}
// cp.async 16B with zero-fill when invalid (src-size = 0)
__device__ __forceinline__ void cpa16(uint32_t saddr, const void* gaddr, bool valid) {
    int sz = valid ? 16 : 0;
    asm volatile("cp.async.cg.shared.global [%0], [%1], 16, %2;"
        :: "r"(saddr), "l"(gaddr), "r"(sz));
}
__device__ __forceinline__ void cpa4(uint32_t saddr, const void* gaddr, bool valid) {
    int sz = valid ? 4 : 0;
    asm volatile("cp.async.ca.shared.global [%0], [%1], 4, %2;"
        :: "r"(saddr), "l"(gaddr), "r"(sz));
}
__device__ __forceinline__ void cpa_commit_wait() {
    asm volatile("cp.async.commit_group;" ::: "memory");
    asm volatile("cp.async.wait_group 0;" ::: "memory");
}

// ------------- weight prepack (all convs, one launch) ----------------
// per-conv layout: [tap][nt][k2][lane] x uint4
__device__ __forceinline__ void pk_one(const float* __restrict__ w, uint32_t* __restrict__ o,
                                       int NT, int CO, int idx) {
    int lane = idx & 31;
    int k2 = (idx >> 5) & 1;
    int nt = (idx >> 6) % NT;
    int tap = idx / (64*NT);
    int lg = lane >> 2, lt = lane & 3;
    int co = nt*8 + lg;
    uint32_t r[4];
    #pragma unroll
    for (int kk = 0; kk < 2; kk++) {
        int c0 = (k2*2 + kk)*16 + lt*2;
        float v0 = (co < CO) ? w[((size_t)co*64 + c0)*9 + tap] : 0.f;
        float v1 = (co < CO) ? w[((size_t)co*64 + c0+1)*9 + tap] : 0.f;
        float v2 = (co < CO) ? w[((size_t)co*64 + c0+8)*9 + tap] : 0.f;
        float v3 = (co < CO) ? w[((size_t)co*64 + c0+9)*9 + tap] : 0.f;
        r[kk*2+0] = pkh2(v0, v1);
        r[kk*2+1] = pkh2(v2, v3);
    }
    ((uint4*)o)[idx] = make_uint4(r[0], r[1], r[2], r[3]);
}

__global__ void prepack_all(
    const float* fx2, const float* fg2, const float* c2,
    const float* fx3, const float* fg3, const float* c3,
    uint32_t* o8, uint32_t* o11, uint32_t* o1)
{
    const int S8 = 9*8*2*32;     // 4608
    const int S11 = 9*11*2*32;   // 6336
    const int S1 = 9*1*2*32;     // 576
    const size_t W8 = (size_t)S8*4, W11 = (size_t)S11*4;
    int idx = blockIdx.x * 256 + threadIdx.x;
    if (idx < S8) { pk_one(fx2, o8, 8, 64, idx); return; }
    idx -= S8;
    if (idx < S8) { pk_one(fg2, o8 + W8, 8, 64, idx); return; }
    idx -= S8;
    if (idx < S8) { pk_one(c2, o8 + 2*W8, 8, 64, idx); return; }
    idx -= S8;
    if (idx < S11) { pk_one(fx3, o11, 11, 81, idx); return; }
    idx -= S11;
    if (idx < S11) { pk_one(fg3, o11 + W11, 11, 81, idx); return; }
    idx -= S11;
    if (idx < S1) { pk_one(c3, o1, 1, 1, idx); return; }
}

// ---------------- conv 3x3, small Cin -> 64 relu, writes fp16 NHWC. Optional 2 heads. ----
// PIX_BLOCKS per head = 4096 = 2^12.
template<int CIN, bool DUAL>
__global__ __launch_bounds__(256) void conv_in_small(
    const float* __restrict__ in0, const float* __restrict__ w0, const float* __restrict__ b0,
    __half* __restrict__ oh0,
    const float* __restrict__ in1, const float* __restrict__ w1, const float* __restrict__ b1,
    __half* __restrict__ oh1)
{
    __shared__ float s_w[64*CIN*9];
    __shared__ float s_b[64];
    int tid = threadIdx.x;
    int head = DUAL ? (int)(blockIdx.x >> 12) : 0;
    const float* in = head ? in1 : in0;
    const float* w  = head ? w1 : w0;
    const float* b  = head ? b1 : b0;
    __half* oh      = head ? oh1 : oh0;

    for (int i = tid; i < 64*CIN*9; i += 256) s_w[i] = w[i];
    if (tid < 64) s_b[tid] = b[tid];
    __syncthreads();

    int px = (DUAL ? (int)(blockIdx.x & 4095) : (int)blockIdx.x)*256 + tid;
    int n = px >> 16; int rem = px & 65535;
    int y = rem >> 8;  int x = rem & 255;

    float iv[CIN*9];
    #pragma unroll
    for (int c = 0; c < CIN; c++)
        #pragma unroll
        for (int kh = 0; kh < 3; kh++)
            #pragma unroll
            for (int kw = 0; kw < 3; kw++) {
                int yy = y + kh - 1, xx = x + kw - 1;
                float v = 0.f;
                if (yy >= 0 && yy < Hh && xx >= 0 && xx < Ww)
                    v = in[((size_t)n*CIN + c)*HW + yy*Ww + xx];
                iv[c*9 + kh*3 + kw] = v;
            }

    float a[64];
    #pragma unroll
    for (int co = 0; co < 64; co++) {
        float s = s_b[co];
        #pragma unroll
        for (int i = 0; i < CIN*9; i++) s += s_w[co*CIN*9 + i] * iv[i];
        a[co] = fmaxf(s, 0.f);
    }

    char* ph = (char*)oh + (size_t)px * 128;
    #pragma unroll
    for (int q = 0; q < 8; q++) {
        uint32_t hw[4];
        #pragma unroll
        for (int t = 0; t < 4; t++)
            hw[t] = pkh2(a[q*8 + t*2], a[q*8 + t*2 + 1]);
        *(uint4*)(ph + q*16) = make_uint4(hw[0], hw[1], hw[2], hw[3]);
    }
}

// ---------------- mma.sync conv 3x3, 64 -> CO, fp16, single pass. -------------------
// CTA tile: 8 y-rows x 32 x (M=256). Warp: 2 y-rows x 32 px = 4 m16 tiles (mt = r*2+h).
// A tile: 10 rows x 34 px x 144B = 48960 B. Staged via cp.async (zero-fill halo).
// MODE: 0 = bias+relu -> fp16 NHWC; 1 = fused softmax+9x9 filter -> xy (window in smem);
//       2 = bias -> fp32 planar (channel 0 only)
// Blocks per head = 16n x 32yq x 8xq = 4096 = 2^12.
template<int NT, int CO, int MODE, bool DUAL>
__global__ __launch_bounds__(128, 2) void conv64m(
    const __half* __restrict__ ih0, const uint32_t* __restrict__ wq0,
    const float* __restrict__ bias0, __half* __restrict__ oh0, const float* __restrict__ fsrc0,
    const __half* __restrict__ ih1, const uint32_t* __restrict__ wq1,
    const float* __restrict__ bias1, __half* __restrict__ oh1, const float* __restrict__ fsrc1,
    float* __restrict__ xy)
{
    constexpr int CP = NT * 8;
    constexpr int AH = 10*34*144;         // 48960 bytes
    extern __shared__ char sm[];
    char* sA = sm;
    float* s_bias = (float*)(sm + AH);
    float* sF = s_bias + CP;              // MODE1: 16 x 40 fp32 zero-padded window

    int tid = threadIdx.x;
    int lane = tid & 31, wid = tid >> 5;
    int lg = lane >> 2, lt = lane & 3;

    int bid = blockIdx.x;
    int head = DUAL ? (bid >> 12) : 0;
    bid &= 4095;                          // 16n x 32yq x 8xq
    const __half* ih = head ? ih1 : ih0;
    const uint32_t* wq = head ? wq1 : wq0;
    const float* bias = head ? bias1 : bias0;
    __half* oh = head ? oh1 : oh0;
    const float* fsrc = head ? fsrc1 : fsrc0;

    int xq = bid & 7;
    int yq = (bid >> 3) & 31;
    int n  = bid >> 8;
    int y0 = yq * 8, x0 = xq * 32;
    size_t nbase = (size_t)n * 65536;

    if (tid < CP) s_bias[tid] = (tid < CO) ? bias[tid] : 0.f;

    uint32_t sA_s = (uint32_t)__cvta_generic_to_shared(sA);

    // stage A tile via cp.async (zero-fill halo = conv zero-padding)
    for (int idx = tid; idx < 10*34*8; idx += 128) {
        int c = idx & 7, e = idx >> 3;
        int row = e / 34, px = e - row*34;
        int gy = y0 + row - 1, gx = x0 + px - 1;
        bool valid = ((unsigned)gy < 256u) && ((unsigned)gx < 256u);
        const char* src = (const char*)ih + (nbase + gy*256 + gx)*128 + c*16;
        cpa16(sA_s + (uint32_t)((row*34 + px)*144 + c*16), src, valid);
    }
    if constexpr (MODE == 1) {
        // stage 9x9 filter source window: rows y0-4..y0+11, cols x0-4..x0+35 (16x40)
        uint32_t sF_s = (uint32_t)__cvta_generic_to_shared(sF);
        const float* sp = fsrc + nbase;
        for (int idx = tid; idx < 16*40; idx += 128) {
            int row = idx / 40, col = idx - row*40;
            int gy = y0 - 4 + row, gx = x0 - 4 + col;
            bool valid = ((unsigned)gy < 256u) && ((unsigned)gx < 256u);
            cpa4(sF_s + (uint32_t)(idx*4), sp + gy*256 + gx, valid);
        }
    }
    cpa_commit_wait();
    __syncthreads();

    float acc[4][NT][4];
    #pragma unroll
    for (int mt = 0; mt < 4; mt++)
        #pragma unroll
        for (int nt = 0; nt < NT; nt++)
            #pragma unroll
            for (int j = 0; j < 4; j++) acc[mt][nt][j] = 0.f;

    uint32_t rbase = (uint32_t)((lane & 15) * 144 + ((lane >> 4) << 4));
    const uint4* wq4 = (const uint4*)wq;

    #pragma unroll 1
    for (int tap = 0; tap < 9; tap++) {
        int kh = tap / 3, kw = tap - kh*3;
        const uint4* wt = wq4 + (size_t)tap*NT*2*32 + lane;
        #pragma unroll
        for (int k2 = 0; k2 < 2; k2++) {
            uint32_t ah[2][4][4];   // [kk][mt][4], mt = r*2 + h
            #pragma unroll
            for (int kk = 0; kk < 2; kk++)
                #pragma unroll
                for (int r = 0; r < 2; r++)
                    #pragma unroll
                    for (int h = 0; h < 2; h++) {
                        uint32_t ad = sA_s +
                            (uint32_t)(((wid*2 + r + kh)*34 + h*16 + kw)*144) +
                            rbase + (k2*2 + kk)*32;
                        ldm_x4(ah[kk][r*2 + h], ad);
                    }
            #pragma unroll
            for (int nt = 0; nt < NT; nt++) {
                uint4 bb = wt[(nt*2 + k2)*32];
                #pragma unroll
                for (int mt = 0; mt < 4; mt++) {
                    mma_f16(acc[mt][nt], ah[0][mt], bb.x, bb.y);
                    mma_f16(acc[mt][nt], ah[1][mt], bb.z, bb.w);
                }
            }
        }
    }

    if constexpr (MODE == 0) {
        // bias + relu + fp16 global
        #pragma unroll
        for (int mt = 0; mt < 4; mt++) {
            int r = mt >> 1, h = mt & 1;
            int Y = y0 + wid*2 + r;
            size_t pix0 = nbase + (size_t)Y*256 + x0 + h*16 + lg;
            #pragma unroll
            for (int nt = 0; nt < NT; nt++) {
                int co = nt*8 + lt*2;
                float b0 = s_bias[co], b1v = s_bias[co+1];
                *(uint32_t*)((char*)oh + pix0*128 + co*2) =
                    pkh2(fmaxf(acc[mt][nt][0] + b0, 0.f), fmaxf(acc[mt][nt][1] + b1v, 0.f));
                *(uint32_t*)((char*)oh + (pix0+8)*128 + co*2) =
                    pkh2(fmaxf(acc[mt][nt][2] + b0, 0.f), fmaxf(acc[mt][nt][3] + b1v, 0.f));
            }
        }
    } else if constexpr (MODE == 1) {
        // fused softmax over 81 logits + 9x9 pixel-adaptive filtering (window in smem)
        #pragma unroll
        for (int mt = 0; mt < 4; mt++) {
            int r = mt >> 1, h = mt & 1;
            int yw = wid*2 + r;                   // window-local y
            #pragma unroll
            for (int rr = 0; rr < 2; rr++) {
                int xw = h*16 + lg + rr*8;        // window-local x (0..31)
                float v[NT][2];
                float mx = -1e30f;
                #pragma unroll
                for (int nt = 0; nt < NT; nt++) {
                    #pragma unroll
                    for (int j = 0; j < 2; j++) {
                        int co = nt*8 + lt*2 + j;
                        v[nt][j] = acc[mt][nt][rr*2 + j] + s_bias[co];
                        if (co < 81) mx = fmaxf(mx, v[nt][j]);
                    }
                }
                mx = fmaxf(mx, __shfl_xor_sync(0xffffffffu, mx, 1));
                mx = fmaxf(mx, __shfl_xor_sync(0xffffffffu, mx, 2));
                float se = 0.f, fo = 0.f;
                #pragma unroll
                for (int nt = 0; nt < NT; nt++) {
                    #pragma unroll
                    for (int j = 0; j < 2; j++) {
                        int co = nt*8 + lt*2 + j;
                        if (co < 81) {
                            float e = __expf(v[nt][j] - mx);
                            se += e;
                            int kh = co / 9, kw = co - kh*9;
                            fo += e * sF[(yw + kh)*40 + xw + kw];
                        }
                    }
                }
                se += __shfl_xor_sync(0xffffffffu, se, 1);
                se += __shfl_xor_sync(0xffffffffu, se, 2);
                fo += __shfl_xor_sync(0xffffffffu, fo, 1);
                fo += __shfl_xor_sync(0xffffffffu, fo, 2);
                if (lt == 0)
                    xy[((size_t)n*2 + head)*HW + (y0 + yw)*256 + x0 + xw] = fo / se;
            }
        }
    } else {
        // MODE 2: fp32 planar out, channel 0 only
        float b0 = s_bias[0];
        if (lt == 0) {
            #pragma unroll
            for (int mt = 0; mt < 4; mt++) {
                int r = mt >> 1, h = mt & 1;
                int Y = y0 + wid*2 + r;
                #pragma unroll
                for (int rr = 0; rr < 2; rr++) {
                    int X = x0 + h*16 + lg + rr*8;
                    xy[nbase + (size_t)Y*256 + X] = acc[mt][0][rr*2] + b0;
                }
            }
        }
    }
}

// ---------------- launch ----------------
extern "C" void kernel_launch(void* const* d_in, const int* in_sizes, int n_in,
                              void* d_out, int out_size)
{
    const float* x     = (const float*)d_in[0];
    const float* g     = (const float*)d_in[1];
    const float* fx_w1 = (const float*)d_in[2];
    const float* fx_b1 = (const float*)d_in[3];
    const float* fx_w2 = (const float*)d_in[4];
    const float* fx_b2 = (const float*)d_in[5];
    const float* fx_w3 = (const float*)d_in[6];
    const float* fx_b3 = (const float*)d_in[7];
    const float* fg_w1 = (const float*)d_in[8];
    const float* fg_b1 = (const float*)d_in[9];
    const float* fg_w2 = (const float*)d_in[10];
    const float* fg_b2 = (const float*)d_in[11];
    const float* fg_w3 = (const float*)d_in[12];
    const float* fg_b3 = (const float*)d_in[13];
    const float* c1_w  = (const float*)d_in[14];
    const float* c1_b  = (const float*)d_in[15];
    const float* c2_w  = (const float*)d_in[16];
    const float* c2_b  = (const float*)d_in[17];
    const float* c3_w  = (const float*)d_in[18];
    const float* c3_b  = (const float*)d_in[19];
    float* out = (float*)d_out;

    __half *h1x, *h1g, *h2x, *h2g;
    float *xy; uint32_t *wq8, *wq11, *wq1;
    cudaGetSymbolAddress((void**)&h1x, g_h1x);
    cudaGetSymbolAddress((void**)&h1g, g_h1g);
    cudaGetSymbolAddress((void**)&h2x, g_h2x);
    cudaGetSymbolAddress((void**)&h2g, g_h2g);
    cudaGetSymbolAddress((void**)&xy, g_xy);
    cudaGetSymbolAddress((void**)&wq8, g_wq8);
    cudaGetSymbolAddress((void**)&wq11, g_wq11);
    cudaGetSymbolAddress((void**)&wq1, g_wq1);

    const size_t W8 = 9*8*2*32*4;
    const size_t W11 = 9*11*2*32*4;
    uint32_t* wq_fx2 = wq8;
    uint32_t* wq_fg2 = wq8 + W8;
    uint32_t* wq_c2  = wq8 + 2*W8;
    uint32_t* wq_fx3 = wq11;
    uint32_t* wq_fg3 = wq11 + W11;

    const int PIX_BLOCKS = Nn*HW/256;      // 4096
    const int C64_BLOCKS = Nn*32*8;        // 4096

    const int AH = 10*34*144;              // 48960
    const int SM64 = AH + 64*4;
    const int SM88 = AH + 88*4 + 16*40*4;  // + filter window
    const int SM8  = AH + 8*4;

    cudaFuncSetAttribute((const void*)conv64m<8, 64, 0, true>,
                         cudaFuncAttributeMaxDynamicSharedMemorySize, SM64);
    cudaFuncSetAttribute((const void*)conv64m<8, 64, 0, false>,
                         cudaFuncAttributeMaxDynamicSharedMemorySize, SM64);
    cudaFuncSetAttribute((const void*)conv64m<11, 81, 1, true>,
                         cudaFuncAttributeMaxDynamicSharedMemorySize, SM88);
    cudaFuncSetAttribute((const void*)conv64m<1, 1, 2, false>,
                         cudaFuncAttributeMaxDynamicSharedMemorySize, SM8);

    // ---- single fused weight prepack ----
    const int PK_TOTAL = 3*(9*8*2*32) + 2*(9*11*2*32) + 9*1*2*32;  // 27072
    prepack_all<<<(PK_TOTAL + 255)/256, 256>>>(
        fx_w2, fg_w2, c2_w, fx_w3, fg_w3, c3_w, wq8, wq11, wq1);

    // ---- batched x+g heads ----
    conv_in_small<1, true><<<2*PIX_BLOCKS, 256>>>(
        x, fx_w1, fx_b1, h1x, g, fg_w1, fg_b1, h1g);
    conv64m<8, 64, 0, true><<<2*C64_BLOCKS, 128, SM64>>>(
        h1x, wq_fx2, fx_b2, h2x, nullptr,
        h1g, wq_fg2, fg_b2, h2g, nullptr, nullptr);
    conv64m<11, 81, 1, true><<<2*C64_BLOCKS, 128, SM88>>>(
        h2x, wq_fx3, fx_b3, nullptr, x,
        h2g, wq_fg3, fg_b3, nullptr, g, xy);

    // ---- fusion head ----
    conv_in_small<2, false><<<PIX_BLOCKS, 256>>>(
        xy, c1_w, c1_b, h1x, nullptr, nullptr, nullptr, nullptr);
    conv64m<8, 64, 0, false><<<C64_BLOCKS, 128, SM64>>>(
        h1x, wq_c2, c2_b, h2x, nullptr,
        nullptr, nullptr, nullptr, nullptr, nullptr, nullptr);
    conv64m<1, 1, 2, false><<<C64_BLOCKS, 128, SM8>>>(
        h2x, wq1, c3_b, nullptr, nullptr,
        nullptr, nullptr, nullptr, nullptr, nullptr, out);
}